// round 6
// baseline (speedup 1.0000x reference)
#include <cuda_runtime.h>
#include <cstdint>
#include <math.h>

// ---------------------------------------------------------------------------
// MoE, tf32 mma.sync + cp.async 3-stage pipeline.
// All internal scratch operands are selected INSIDE device code via template
// codes (passing __device__ symbols from host was the R4 bug).
//   convert: round x + all weights to tf32 bits once
//   gate -> offsets -> scatter (fp32, exact routing)
//   GEMM1 routed SwiGLU (gather, dual-B) -> g_h   (tf32-rounded at store)
//   GEMM2 routed down                    -> g_rout
//   GEMM3 shared SwiGLU (dual-B)         -> g_hs  (tf32-rounded at store)
//   GEMM4 shared down                    -> d_out
//   combine: out += w0*rout[s0] + w1*rout[s1]
// GEMM: block 64x128, 8 warps (2x4), warp 32x32, mma.m16n8k8 tf32,
//       cp.async.ca 16B, 3 smem stages, one __syncthreads per stage.
// ---------------------------------------------------------------------------

namespace {
constexpr int T     = 2048;
constexpr int DIMC  = 1024;
constexpr int E     = 16;
constexpr int NP    = T * 2;
constexpr int INTER = 512;
constexpr int SI    = 1024;

constexpr int BM = 64, BN = 128, BK = 16;
constexpr int PAD = 12;
constexpr int STAGES = 3;
constexpr int ABUF = 2 * BM * PAD;   // u32 per stage
constexpr int BBUF = 2 * BN * PAD;

constexpr size_t NX = (size_t)T * DIMC;
constexpr size_t NW = (size_t)E * INTER * DIMC;
constexpr size_t NS = (size_t)SI * DIMC;
}

__device__ int   g_count[E];
__device__ int   g_offset[E];
__device__ int   g_fill[E];
__device__ int   g_pair_e[NP];
__device__ float g_pair_w[NP];
__device__ int   g_slot_of_pair[NP];
__device__ int   g_tok_of_slot[NP];
__device__ __align__(16) float g_h[(size_t)NP * INTER];
__device__ __align__(16) float g_rout[(size_t)NP * DIMC];
__device__ __align__(16) float g_hs[(size_t)T * SI];

// tf32-rounded operand copies
__device__ __align__(16) float g_xc [NX];
__device__ __align__(16) float g_w1c[NW];
__device__ __align__(16) float g_w2c[NW];
__device__ __align__(16) float g_w3c[NW];
__device__ __align__(16) float g_sw1c[NS];
__device__ __align__(16) float g_sw2c[NS];
__device__ __align__(16) float g_sw3c[NS];

// ---------------- helpers ----------------
__device__ __forceinline__ uint32_t f2tf32(float f) {
    uint32_t r;
    asm("cvt.rna.tf32.f32 %0, %1;" : "=r"(r) : "f"(f));
    return r;
}
__device__ __forceinline__ uint32_t smem_u32(const void* p) {
    uint32_t a;
    asm("{ .reg .u64 t; cvta.to.shared.u64 t, %1; cvt.u32.u64 %0, t; }" : "=r"(a) : "l"(p));
    return a;
}
__device__ __forceinline__ void mma8(float* c, const uint32_t* a, const uint32_t* b) {
    asm volatile(
        "mma.sync.aligned.m16n8k8.row.col.f32.tf32.tf32.f32 "
        "{%0,%1,%2,%3},{%4,%5,%6,%7},{%8,%9},{%0,%1,%2,%3};"
        : "+f"(c[0]), "+f"(c[1]), "+f"(c[2]), "+f"(c[3])
        : "r"(a[0]), "r"(a[1]), "r"(a[2]), "r"(a[3]), "r"(b[0]), "r"(b[1]));
}
#define CP_A16(dst, src) asm volatile("cp.async.ca.shared.global [%0], [%1], 16;" :: "r"(dst), "l"(src))
#define CP_COMMIT()      asm volatile("cp.async.commit_group;" ::: "memory")
#define CP_WAIT1()       asm volatile("cp.async.wait_group 1;" ::: "memory")

// ---------------- convert ----------------
__global__ __launch_bounds__(256) void convert_kernel(
    const float* __restrict__ x,  const float* __restrict__ w1,
    const float* __restrict__ w2, const float* __restrict__ w3,
    const float* __restrict__ sw1, const float* __restrict__ sw2,
    const float* __restrict__ sw3) {
    size_t q = ((size_t)blockIdx.x * blockDim.x + threadIdx.x) * 4;
    const float* src;
    float* dst;
    size_t off;
    if      (q < NX)               { src = x;   dst = g_xc;   off = q; }
    else if (q < NX + NW)          { src = w1;  dst = g_w1c;  off = q - NX; }
    else if (q < NX + 2*NW)        { src = w2;  dst = g_w2c;  off = q - NX - NW; }
    else if (q < NX + 3*NW)        { src = w3;  dst = g_w3c;  off = q - NX - 2*NW; }
    else if (q < NX + 3*NW + NS)   { src = sw1; dst = g_sw1c; off = q - NX - 3*NW; }
    else if (q < NX + 3*NW + 2*NS) { src = sw2; dst = g_sw2c; off = q - NX - 3*NW - NS; }
    else                           { src = sw3; dst = g_sw3c; off = q - NX - 3*NW - 2*NS; }
    float4 v = *(const float4*)(src + off);
    uint4 o;
    o.x = f2tf32(v.x); o.y = f2tf32(v.y); o.z = f2tf32(v.z); o.w = f2tf32(v.w);
    *(uint4*)(dst + off) = o;
}

// ---------------- routing ----------------
__global__ void reset_kernel() {
    if (threadIdx.x < E) g_count[threadIdx.x] = 0;
}

__global__ __launch_bounds__(128) void gate_kernel(const float* __restrict__ x,
                                                   const float* __restrict__ gw) {
    __shared__ float xs[DIMC];
    __shared__ float part[8][E];
    __shared__ float logit[E];
    int t = blockIdx.x;
    for (int i = threadIdx.x; i < DIMC; i += 128) xs[i] = x[(size_t)t * DIMC + i];
    __syncthreads();
    int e = threadIdx.x & 15, chunk = threadIdx.x >> 4;
    const float* gr = gw + (size_t)e * DIMC + chunk * 128;
    const float* xr = xs + chunk * 128;
    float a0 = 0.f, a1 = 0.f, a2 = 0.f, a3 = 0.f;
    #pragma unroll 8
    for (int i = 0; i < 128; i += 4) {
        a0 += xr[i+0] * gr[i+0]; a1 += xr[i+1] * gr[i+1];
        a2 += xr[i+2] * gr[i+2]; a3 += xr[i+3] * gr[i+3];
    }
    part[chunk][e] = (a0 + a1) + (a2 + a3);
    __syncthreads();
    if (threadIdx.x < E) {
        float s = 0.f;
        #pragma unroll
        for (int c = 0; c < 8; c++) s += part[c][threadIdx.x];
        logit[threadIdx.x] = s;
    }
    __syncthreads();
    if (threadIdx.x == 0) {
        int i0 = 0; float v0 = logit[0];
        #pragma unroll
        for (int i = 1; i < E; i++) if (logit[i] > v0) { v0 = logit[i]; i0 = i; }
        int i1 = -1; float v1 = -1e30f;
        #pragma unroll
        for (int i = 0; i < E; i++) if (i != i0 && logit[i] > v1) { v1 = logit[i]; i1 = i; }
        float s0 = 1.f / (1.f + expf(-v0));
        float s1 = 1.f / (1.f + expf(-v1));
        float inv = 1.f / (s0 + s1);
        g_pair_e[t*2+0] = i0; g_pair_w[t*2+0] = s0 * inv;
        g_pair_e[t*2+1] = i1; g_pair_w[t*2+1] = s1 * inv;
        atomicAdd(&g_count[i0], 1);
        atomicAdd(&g_count[i1], 1);
    }
}

__global__ void offsets_kernel() {
    if (threadIdx.x == 0) {
        int s = 0;
        for (int e = 0; e < E; e++) { g_offset[e] = s; s += g_count[e]; g_fill[e] = 0; }
    }
}

__global__ void scatter_kernel() {
    int p = blockIdx.x * blockDim.x + threadIdx.x;
    if (p >= NP) return;
    int e = g_pair_e[p];
    int slot = g_offset[e] + atomicAdd(&g_fill[e], 1);
    g_slot_of_pair[p] = slot;
    g_tok_of_slot[slot] = p >> 1;
}

// ---------------------------------------------------------------------------
// Pipelined tf32 GEMM: C[M,N] = A[M,K] @ B[N,K]^T (+ dual-B SwiGLU)
//   ASRC: 0=g_xc, 1=g_h, 2=g_hs
//   BSRC: 0=(g_w1c,g_w3c), 1=g_w2c, 2=(g_sw1c,g_sw3c), 3=g_sw2c
//   CDST: 0=g_h, 1=g_rout, 2=g_hs, 3=Cext
// ---------------------------------------------------------------------------
template<int KD, bool DUAL, bool ROUTED, bool GATHER, int ASRC, int BSRC, int CDST>
__global__ __launch_bounds__(256, 2) void gemm_mma(float* __restrict__ Cext, int Ntot) {
    extern __shared__ uint32_t sm[];
    uint32_t* As  = sm;
    uint32_t* B1s = sm + STAGES * ABUF;
    uint32_t* B3s = B1s + STAGES * BBUF;
    __shared__ int rowsS[BM];

    const int e   = ROUTED ? blockIdx.z : 0;
    const int cnt = ROUTED ? g_count[e] : T;
    const int m0  = blockIdx.x * BM;
    if (m0 >= cnt) return;
    const int n0   = blockIdx.y * BN;
    const int base = ROUTED ? g_offset[e] : 0;

    const float* A = (ASRC == 0) ? g_xc : (ASRC == 1 ? g_h : g_hs);
    float* C = (CDST == 0) ? g_h : (CDST == 1 ? g_rout : (CDST == 2 ? g_hs : Cext));
    const float* B1base_g = (BSRC == 0) ? g_w1c : (BSRC == 1 ? g_w2c : (BSRC == 2 ? g_sw1c : g_sw2c));
    const float* B3base_g = (BSRC == 0) ? g_w3c : (BSRC == 2 ? g_sw3c : nullptr);
    const float* B1 = B1base_g + (size_t)(ROUTED ? e : 0) * Ntot * KD;
    const float* B3 = DUAL ? (B3base_g + (size_t)(ROUTED ? e : 0) * Ntot * KD) : nullptr;

    const int tid    = threadIdx.x;
    const int wid    = tid >> 5;
    const int lane   = tid & 31;
    const int lane4  = lane >> 2;
    const int lanek  = lane & 3;
    const int warp_m = wid & 1;
    const int warp_n = wid >> 1;

    if (tid < BM) {
        int m = m0 + tid;
        int r;
        if (m >= cnt)    r = GATHER ? g_tok_of_slot[base] : base;
        else if (GATHER) r = g_tok_of_slot[base + m];
        else if (ROUTED) r = base + m;
        else             r = m;
        rowsS[tid] = r;
    }
    __syncthreads();

    const int lr = tid >> 2;
    const int lq = tid & 3;
    const int lg = lq >> 1;
    const int lk = (lq & 1) * 4;
    const int a_row = rowsS[lr];
    const float* aload = A  + (size_t)a_row * KD + lg * 8 + lk;
    const float* b1l0  = B1 + (size_t)(n0 + lr)      * KD + lg * 8 + lk;
    const float* b1l1  = B1 + (size_t)(n0 + lr + 64) * KD + lg * 8 + lk;
    const float* b3l0  = DUAL ? (B3 + (size_t)(n0 + lr)      * KD + lg * 8 + lk) : nullptr;
    const float* b3l1  = DUAL ? (B3 + (size_t)(n0 + lr + 64) * KD + lg * 8 + lk) : nullptr;

    const uint32_t aA  = smem_u32(As)  + ((lg * BM + lr) * PAD + lk) * 4;
    const uint32_t aB0 = smem_u32(B1s) + ((lg * BN + lr) * PAD + lk) * 4;
    const uint32_t aB1 = smem_u32(B1s) + ((lg * BN + lr + 64) * PAD + lk) * 4;
    const uint32_t aC0 = DUAL ? (smem_u32(B3s) + ((lg * BN + lr) * PAD + lk) * 4) : 0;
    const uint32_t aC1 = DUAL ? (smem_u32(B3s) + ((lg * BN + lr + 64) * PAD + lk) * 4) : 0;

    auto issue = [&](int k0, int st) {
        if (k0 < KD) {
            CP_A16(aA  + st * (ABUF * 4), aload + k0);
            CP_A16(aB0 + st * (BBUF * 4), b1l0 + k0);
            CP_A16(aB1 + st * (BBUF * 4), b1l1 + k0);
            if (DUAL) {
                CP_A16(aC0 + st * (BBUF * 4), b3l0 + k0);
                CP_A16(aC1 + st * (BBUF * 4), b3l1 + k0);
            }
        }
        CP_COMMIT();
    };

    issue(0, 0);
    issue(BK, 1);

    float acc1[2][4][4] = {};
    float acc3[2][4][4] = {};

    int st = 0;
    for (int k0 = 0; k0 < KD; k0 += BK) {
        CP_WAIT1();
        __syncthreads();

        const uint32_t* Abase  = As  + st * ABUF;
        const uint32_t* B1base = B1s + st * BBUF;
        const uint32_t* B3base = DUAL ? (B3s + st * BBUF) : nullptr;

        #pragma unroll
        for (int ks = 0; ks < 2; ks++) {
            const uint32_t* Ab  = Abase  + ks * BM * PAD;
            const uint32_t* B1b = B1base + ks * BN * PAD;
            const uint32_t* B3b = DUAL ? (B3base + ks * BN * PAD) : nullptr;
            uint32_t af[2][4];
            #pragma unroll
            for (int fm = 0; fm < 2; fm++) {
                int rbase = (warp_m * 32 + fm * 16 + lane4) * PAD + lanek;
                af[fm][0] = Ab[rbase];
                af[fm][1] = Ab[rbase + 8 * PAD];
                af[fm][2] = Ab[rbase + 4];
                af[fm][3] = Ab[rbase + 8 * PAD + 4];
            }
            #pragma unroll
            for (int fn = 0; fn < 4; fn++) {
                int nbase = (warp_n * 32 + fn * 8 + lane4) * PAD + lanek;
                uint32_t bf[2];
                bf[0] = B1b[nbase];
                bf[1] = B1b[nbase + 4];
                #pragma unroll
                for (int fm = 0; fm < 2; fm++) mma8(acc1[fm][fn], af[fm], bf);
                if (DUAL) {
                    uint32_t cf[2];
                    cf[0] = B3b[nbase];
                    cf[1] = B3b[nbase + 4];
                    #pragma unroll
                    for (int fm = 0; fm < 2; fm++) mma8(acc3[fm][fn], af[fm], cf);
                }
            }
        }
        issue(k0 + 2 * BK, (k0 / BK + 2) % STAGES);
        st = (st + 1 == STAGES) ? 0 : st + 1;
    }

    // epilogue
    #pragma unroll
    for (int fm = 0; fm < 2; fm++) {
        #pragma unroll
        for (int half = 0; half < 2; half++) {
            int mi = warp_m * 32 + fm * 16 + half * 8 + lane4;
            int m  = m0 + mi;
            if (m >= cnt) continue;
            size_t crow = ROUTED ? (size_t)(base + m) : (size_t)m;
            float* cp = C + crow * Ntot + n0 + warp_n * 32 + lanek * 2;
            #pragma unroll
            for (int fn = 0; fn < 4; fn++) {
                float v0 = acc1[fm][fn][half * 2 + 0];
                float v1 = acc1[fm][fn][half * 2 + 1];
                float2 o;
                if (DUAL) {
                    float s0 = (v0 / (1.f + __expf(-v0))) * acc3[fm][fn][half * 2 + 0];
                    float s1 = (v1 / (1.f + __expf(-v1))) * acc3[fm][fn][half * 2 + 1];
                    o.x = __uint_as_float(f2tf32(s0));
                    o.y = __uint_as_float(f2tf32(s1));
                } else {
                    o.x = v0; o.y = v1;
                }
                *(float2*)(cp + fn * 8) = o;
            }
        }
    }
}

__global__ __launch_bounds__(256) void combine_kernel(float* __restrict__ out) {
    int t = blockIdx.x;
    float w0 = g_pair_w[t*2+0], w1 = g_pair_w[t*2+1];
    size_t s0 = (size_t)g_slot_of_pair[t*2+0] * DIMC;
    size_t s1 = (size_t)g_slot_of_pair[t*2+1] * DIMC;
    int d = threadIdx.x * 4;
    float4 o  = *(float4*)(out + (size_t)t * DIMC + d);
    float4 r0 = *(const float4*)(g_rout + s0 + d);
    float4 r1 = *(const float4*)(g_rout + s1 + d);
    o.x += w0 * r0.x + w1 * r1.x;
    o.y += w0 * r0.y + w1 * r1.y;
    o.z += w0 * r0.z + w1 * r1.z;
    o.w += w0 * r0.w + w1 * r1.w;
    *(float4*)(out + (size_t)t * DIMC + d) = o;
}

// ---------------------------------------------------------------------------
extern "C" void kernel_launch(void* const* d_in, const int* in_sizes, int n_in,
                              void* d_out, int out_size) {
    const float* x      = (const float*)d_in[0];
    const float* gate_w = (const float*)d_in[1];
    const float* w1     = (const float*)d_in[2];
    const float* w2     = (const float*)d_in[3];
    const float* w3     = (const float*)d_in[4];
    const float* sw1    = (const float*)d_in[5];
    const float* sw2    = (const float*)d_in[6];
    const float* sw3    = (const float*)d_in[7];
    float* out = (float*)d_out;

    auto g1 = gemm_mma<DIMC, true,  true,  true,  0, 0, 0>;
    auto g2 = gemm_mma<INTER, false, true,  false, 1, 1, 1>;
    auto g3 = gemm_mma<DIMC, true,  false, false, 0, 2, 2>;
    auto g4 = gemm_mma<SI,   false, false, false, 2, 3, 3>;
    constexpr int SMEM_DUAL = (STAGES * (ABUF + 2 * BBUF)) * 4;  // 92160
    constexpr int SMEM_SNGL = (STAGES * (ABUF + BBUF)) * 4;      // 55296
    cudaFuncSetAttribute(g1, cudaFuncAttributeMaxDynamicSharedMemorySize, SMEM_DUAL);
    cudaFuncSetAttribute(g2, cudaFuncAttributeMaxDynamicSharedMemorySize, SMEM_SNGL);
    cudaFuncSetAttribute(g3, cudaFuncAttributeMaxDynamicSharedMemorySize, SMEM_DUAL);
    cudaFuncSetAttribute(g4, cudaFuncAttributeMaxDynamicSharedMemorySize, SMEM_SNGL);

    convert_kernel<<<(int)((NX + 3*NW + 3*NS) / 4 / 256), 256>>>(x, w1, w2, w3, sw1, sw2, sw3);
    reset_kernel<<<1, 32>>>();
    gate_kernel<<<T, 128>>>(x, gate_w);
    offsets_kernel<<<1, 32>>>();
    scatter_kernel<<<NP / 256, 256>>>();

    g1<<<dim3(T / BM, INTER / BN, E), 256, SMEM_DUAL>>>(nullptr, INTER);
    g2<<<dim3(T / BM, DIMC / BN, E), 256, SMEM_SNGL>>>(nullptr, DIMC);
    g3<<<dim3(T / BM, SI / BN, 1), 256, SMEM_DUAL>>>(nullptr, SI);
    g4<<<dim3(T / BM, DIMC / BN, 1), 256, SMEM_SNGL>>>(out, DIMC);

    combine_kernel<<<T, 256>>>(out);
}

// round 10
// speedup vs baseline: 1.0718x; 1.0718x over previous
#include <cuda_runtime.h>
#include <cstdint>
#include <math.h>

// ---------------------------------------------------------------------------
// MoE, tf32 mma.sync + cp.async 3-stage pipeline.
//   reset -> gate -> scatter(+offsets)
//   swiglu_gemm (merged): z<16 routed SwiGLU (gather) -> g_h ; z==16 shared -> g_hs
//   down_gemm   (merged): z<16 routed down -> g_rout  ; z==16 shared down -> d_out
//   combine: out += w0*rout[s0] + w1*rout[s1]
// tf32 rounding (cvt.rna) applied to fragment registers at consume time
// (fma/alu pipes are idle under the tensor pipe -> free), no convert pass.
// GEMM: block 64x128, 8 warps (2x4), warp 32x32, mma.m16n8k8 tf32,
//       cp.async.ca 16B, 3 smem stages.
// ---------------------------------------------------------------------------

namespace {
constexpr int T     = 2048;
constexpr int DIMC  = 1024;
constexpr int E     = 16;
constexpr int NP    = T * 2;
constexpr int INTER = 512;
constexpr int SI    = 1024;

constexpr int BM = 64, BN = 128, BK = 16;
constexpr int PAD = 12;
constexpr int STAGES = 3;
constexpr int ABUF = 2 * BM * PAD;   // u32 per stage
constexpr int BBUF = 2 * BN * PAD;
constexpr int SMEM_DUAL = (STAGES * (ABUF + 2 * BBUF)) * 4;
constexpr int SMEM_SNGL = (STAGES * (ABUF + BBUF)) * 4;
}

__device__ int   g_count[E];
__device__ int   g_offset[E];
__device__ int   g_fill[E];
__device__ int   g_pair_e[NP];
__device__ float g_pair_w[NP];
__device__ int   g_slot_of_pair[NP];
__device__ int   g_tok_of_slot[NP];
__device__ __align__(16) float g_h[(size_t)NP * INTER];
__device__ __align__(16) float g_rout[(size_t)NP * DIMC];
__device__ __align__(16) float g_hs[(size_t)T * SI];

// ---------------- helpers ----------------
__device__ __forceinline__ uint32_t f2tf32(float f) {
    uint32_t r;
    asm("cvt.rna.tf32.f32 %0, %1;" : "=r"(r) : "f"(f));
    return r;
}
__device__ __forceinline__ uint32_t u2tf32(uint32_t u) {
    uint32_t r;
    asm("cvt.rna.tf32.f32 %0, %1;" : "=r"(r) : "f"(__uint_as_float(u)));
    return r;
}
__device__ __forceinline__ uint32_t smem_u32(const void* p) {
    uint32_t a;
    asm("{ .reg .u64 t; cvta.to.shared.u64 t, %1; cvt.u32.u64 %0, t; }" : "=r"(a) : "l"(p));
    return a;
}
__device__ __forceinline__ void mma8(float* c, const uint32_t* a, const uint32_t* b) {
    asm volatile(
        "mma.sync.aligned.m16n8k8.row.col.f32.tf32.tf32.f32 "
        "{%0,%1,%2,%3},{%4,%5,%6,%7},{%8,%9},{%0,%1,%2,%3};"
        : "+f"(c[0]), "+f"(c[1]), "+f"(c[2]), "+f"(c[3])
        : "r"(a[0]), "r"(a[1]), "r"(a[2]), "r"(a[3]), "r"(b[0]), "r"(b[1]));
}
#define CP_A16(dst, src) asm volatile("cp.async.ca.shared.global [%0], [%1], 16;" :: "r"(dst), "l"(src))
#define CP_COMMIT()      asm volatile("cp.async.commit_group;" ::: "memory")
#define CP_WAIT1()       asm volatile("cp.async.wait_group 1;" ::: "memory")

// ---------------- routing ----------------
__global__ void reset_kernel() {
    if (threadIdx.x < E) g_count[threadIdx.x] = 0;
}

__global__ __launch_bounds__(128) void gate_kernel(const float* __restrict__ x,
                                                   const float* __restrict__ gw) {
    __shared__ float xs[DIMC];
    __shared__ float part[8][E];
    __shared__ float logit[E];
    int t = blockIdx.x;
    for (int i = threadIdx.x; i < DIMC; i += 128) xs[i] = x[(size_t)t * DIMC + i];
    __syncthreads();
    int e = threadIdx.x & 15, chunk = threadIdx.x >> 4;
    const float* gr = gw + (size_t)e * DIMC + chunk * 128;
    const float* xr = xs + chunk * 128;
    float a0 = 0.f, a1 = 0.f, a2 = 0.f, a3 = 0.f;
    #pragma unroll 8
    for (int i = 0; i < 128; i += 4) {
        a0 += xr[i+0] * gr[i+0]; a1 += xr[i+1] * gr[i+1];
        a2 += xr[i+2] * gr[i+2]; a3 += xr[i+3] * gr[i+3];
    }
    part[chunk][e] = (a0 + a1) + (a2 + a3);
    __syncthreads();
    if (threadIdx.x < E) {
        float s = 0.f;
        #pragma unroll
        for (int c = 0; c < 8; c++) s += part[c][threadIdx.x];
        logit[threadIdx.x] = s;
    }
    __syncthreads();
    if (threadIdx.x == 0) {
        int i0 = 0; float v0 = logit[0];
        #pragma unroll
        for (int i = 1; i < E; i++) if (logit[i] > v0) { v0 = logit[i]; i0 = i; }
        int i1 = -1; float v1 = -1e30f;
        #pragma unroll
        for (int i = 0; i < E; i++) if (i != i0 && logit[i] > v1) { v1 = logit[i]; i1 = i; }
        float s0 = 1.f / (1.f + expf(-v0));
        float s1 = 1.f / (1.f + expf(-v1));
        float inv = 1.f / (s0 + s1);
        g_pair_e[t*2+0] = i0; g_pair_w[t*2+0] = s0 * inv;
        g_pair_e[t*2+1] = i1; g_pair_w[t*2+1] = s1 * inv;
        atomicAdd(&g_count[i0], 1);
        atomicAdd(&g_count[i1], 1);
    }
}

// offsets + scatter in one single-block kernel
__global__ __launch_bounds__(1024) void scatter_kernel() {
    if (threadIdx.x == 0) {
        int s = 0;
        #pragma unroll
        for (int e = 0; e < E; e++) { g_offset[e] = s; s += g_count[e]; g_fill[e] = 0; }
    }
    __syncthreads();
    for (int p = threadIdx.x; p < NP; p += 1024) {
        int e = g_pair_e[p];
        int slot = g_offset[e] + atomicAdd(&g_fill[e], 1);
        g_slot_of_pair[p] = slot;
        g_tok_of_slot[slot] = p >> 1;
    }
}

// ---------------------------------------------------------------------------
// Merged SwiGLU GEMM (dual-B). z<16: routed expert z, z==16: shared expert.
// A = x (raw fp32, rounded at consume). KD = DIMC for both.
// ---------------------------------------------------------------------------
__global__ __launch_bounds__(256, 2) void swiglu_gemm(const float* __restrict__ x,
                                                      const float* __restrict__ w1,
                                                      const float* __restrict__ w3,
                                                      const float* __restrict__ sw1,
                                                      const float* __restrict__ sw3) {
    extern __shared__ uint32_t sm[];
    uint32_t* As  = sm;
    uint32_t* B1s = sm + STAGES * ABUF;
    uint32_t* B3s = B1s + STAGES * BBUF;
    __shared__ int rowsS[BM];

    const int z      = blockIdx.z;
    const bool routed = (z < E);
    const int  Ntot  = routed ? INTER : SI;
    if (blockIdx.y * BN >= Ntot) return;
    const int cnt  = routed ? g_count[z] : T;
    const int m0   = blockIdx.x * BM;
    if (m0 >= cnt) return;
    const int n0   = blockIdx.y * BN;
    const int base = routed ? g_offset[z] : 0;

    const float* B1 = routed ? (w1 + (size_t)z * INTER * DIMC) : sw1;
    const float* B3 = routed ? (w3 + (size_t)z * INTER * DIMC) : sw3;
    float* C = routed ? g_h : g_hs;

    const int tid    = threadIdx.x;
    const int wid    = tid >> 5;
    const int lane   = tid & 31;
    const int lane4  = lane >> 2;
    const int lanek  = lane & 3;
    const int warp_m = wid & 1;
    const int warp_n = wid >> 1;

    if (tid < BM) {
        int m = m0 + tid;
        int r;
        if (routed) r = (m < cnt) ? g_tok_of_slot[base + m] : g_tok_of_slot[base];
        else        r = (m < cnt) ? m : 0;
        rowsS[tid] = r;
    }
    __syncthreads();

    const int lr = tid >> 2;
    const int lq = tid & 3;
    const int lg = lq >> 1;
    const int lk = (lq & 1) * 4;
    const float* aload = x  + (size_t)rowsS[lr] * DIMC + lg * 8 + lk;
    const float* b1l0  = B1 + (size_t)(n0 + lr)      * DIMC + lg * 8 + lk;
    const float* b1l1  = B1 + (size_t)(n0 + lr + 64) * DIMC + lg * 8 + lk;
    const float* b3l0  = B3 + (size_t)(n0 + lr)      * DIMC + lg * 8 + lk;
    const float* b3l1  = B3 + (size_t)(n0 + lr + 64) * DIMC + lg * 8 + lk;

    const uint32_t aA  = smem_u32(As)  + ((lg * BM + lr) * PAD + lk) * 4;
    const uint32_t aB0 = smem_u32(B1s) + ((lg * BN + lr) * PAD + lk) * 4;
    const uint32_t aB1 = smem_u32(B1s) + ((lg * BN + lr + 64) * PAD + lk) * 4;
    const uint32_t aC0 = smem_u32(B3s) + ((lg * BN + lr) * PAD + lk) * 4;
    const uint32_t aC1 = smem_u32(B3s) + ((lg * BN + lr + 64) * PAD + lk) * 4;

    auto issue = [&](int k0, int st) {
        if (k0 < DIMC) {
            CP_A16(aA  + st * (ABUF * 4), aload + k0);
            CP_A16(aB0 + st * (BBUF * 4), b1l0 + k0);
            CP_A16(aB1 + st * (BBUF * 4), b1l1 + k0);
            CP_A16(aC0 + st * (BBUF * 4), b3l0 + k0);
            CP_A16(aC1 + st * (BBUF * 4), b3l1 + k0);
        }
        CP_COMMIT();
    };

    issue(0, 0);
    issue(BK, 1);

    float acc1[2][4][4] = {};
    float acc3[2][4][4] = {};

    int st = 0;
    for (int k0 = 0; k0 < DIMC; k0 += BK) {
        CP_WAIT1();
        __syncthreads();

        const uint32_t* Abase  = As  + st * ABUF;
        const uint32_t* B1base = B1s + st * BBUF;
        const uint32_t* B3base = B3s + st * BBUF;

        #pragma unroll
        for (int ks = 0; ks < 2; ks++) {
            const uint32_t* Ab  = Abase  + ks * BM * PAD;
            const uint32_t* B1b = B1base + ks * BN * PAD;
            const uint32_t* B3b = B3base + ks * BN * PAD;
            uint32_t af[2][4];
            #pragma unroll
            for (int fm = 0; fm < 2; fm++) {
                int rbase = (warp_m * 32 + fm * 16 + lane4) * PAD + lanek;
                af[fm][0] = u2tf32(Ab[rbase]);
                af[fm][1] = u2tf32(Ab[rbase + 8 * PAD]);
                af[fm][2] = u2tf32(Ab[rbase + 4]);
                af[fm][3] = u2tf32(Ab[rbase + 8 * PAD + 4]);
            }
            #pragma unroll
            for (int fn = 0; fn < 4; fn++) {
                int nbase = (warp_n * 32 + fn * 8 + lane4) * PAD + lanek;
                uint32_t bf[2], cf[2];
                bf[0] = u2tf32(B1b[nbase]);
                bf[1] = u2tf32(B1b[nbase + 4]);
                cf[0] = u2tf32(B3b[nbase]);
                cf[1] = u2tf32(B3b[nbase + 4]);
                #pragma unroll
                for (int fm = 0; fm < 2; fm++) {
                    mma8(acc1[fm][fn], af[fm], bf);
                    mma8(acc3[fm][fn], af[fm], cf);
                }
            }
        }
        issue(k0 + 2 * BK, (k0 / BK + 2) % STAGES);
        st = (st + 1 == STAGES) ? 0 : st + 1;
    }

    // epilogue: SwiGLU, store fp32 (consumer rounds at its own load)
    #pragma unroll
    for (int fm = 0; fm < 2; fm++) {
        #pragma unroll
        for (int half = 0; half < 2; half++) {
            int mi = warp_m * 32 + fm * 16 + half * 8 + lane4;
            int m  = m0 + mi;
            if (m >= cnt) continue;
            size_t crow = routed ? (size_t)(base + m) : (size_t)m;
            float* cp = C + crow * Ntot + n0 + warp_n * 32 + lanek * 2;
            #pragma unroll
            for (int fn = 0; fn < 4; fn++) {
                float v0 = acc1[fm][fn][half * 2 + 0];
                float v1 = acc1[fm][fn][half * 2 + 1];
                float2 o;
                o.x = (v0 / (1.f + __expf(-v0))) * acc3[fm][fn][half * 2 + 0];
                o.y = (v1 / (1.f + __expf(-v1))) * acc3[fm][fn][half * 2 + 1];
                *(float2*)(cp + fn * 8) = o;
            }
        }
    }
}

// ---------------------------------------------------------------------------
// Merged down GEMM. z<16: routed (A=g_h, KD=512) -> g_rout.
//                   z==16: shared (A=g_hs, KD=1024) -> out.
// ---------------------------------------------------------------------------
__global__ __launch_bounds__(256, 2) void down_gemm(const float* __restrict__ w2,
                                                    const float* __restrict__ sw2,
                                                    float* __restrict__ out) {
    extern __shared__ uint32_t sm[];
    uint32_t* As  = sm;
    uint32_t* B1s = sm + STAGES * ABUF;
    __shared__ int rowsS[BM];

    const int z       = blockIdx.z;
    const bool routed = (z < E);
    const int  KD     = routed ? INTER : SI;
    const int cnt  = routed ? g_count[z] : T;
    const int m0   = blockIdx.x * BM;
    if (m0 >= cnt) return;
    const int n0   = blockIdx.y * BN;
    const int base = routed ? g_offset[z] : 0;

    const float* A  = routed ? g_h : g_hs;
    const float* B1 = routed ? (w2 + (size_t)z * DIMC * INTER) : sw2;
    float* C = routed ? g_rout : out;

    const int tid    = threadIdx.x;
    const int wid    = tid >> 5;
    const int lane   = tid & 31;
    const int lane4  = lane >> 2;
    const int lanek  = lane & 3;
    const int warp_m = wid & 1;
    const int warp_n = wid >> 1;

    if (tid < BM) {
        int m = m0 + tid;
        rowsS[tid] = (m < cnt) ? (routed ? base + m : m) : (routed ? base : 0);
    }
    __syncthreads();

    const int lr = tid >> 2;
    const int lq = tid & 3;
    const int lg = lq >> 1;
    const int lk = (lq & 1) * 4;
    const float* aload = A  + (size_t)rowsS[lr] * KD + lg * 8 + lk;
    const float* b1l0  = B1 + (size_t)(n0 + lr)      * KD + lg * 8 + lk;
    const float* b1l1  = B1 + (size_t)(n0 + lr + 64) * KD + lg * 8 + lk;

    const uint32_t aA  = smem_u32(As)  + ((lg * BM + lr) * PAD + lk) * 4;
    const uint32_t aB0 = smem_u32(B1s) + ((lg * BN + lr) * PAD + lk) * 4;
    const uint32_t aB1 = smem_u32(B1s) + ((lg * BN + lr + 64) * PAD + lk) * 4;

    auto issue = [&](int k0, int st) {
        if (k0 < KD) {
            CP_A16(aA  + st * (ABUF * 4), aload + k0);
            CP_A16(aB0 + st * (BBUF * 4), b1l0 + k0);
            CP_A16(aB1 + st * (BBUF * 4), b1l1 + k0);
        }
        CP_COMMIT();
    };

    issue(0, 0);
    issue(BK, 1);

    float acc1[2][4][4] = {};

    int st = 0;
    for (int k0 = 0; k0 < KD; k0 += BK) {
        CP_WAIT1();
        __syncthreads();

        const uint32_t* Abase  = As  + st * ABUF;
        const uint32_t* B1base = B1s + st * BBUF;

        #pragma unroll
        for (int ks = 0; ks < 2; ks++) {
            const uint32_t* Ab  = Abase  + ks * BM * PAD;
            const uint32_t* B1b = B1base + ks * BN * PAD;
            uint32_t af[2][4];
            #pragma unroll
            for (int fm = 0; fm < 2; fm++) {
                int rbase = (warp_m * 32 + fm * 16 + lane4) * PAD + lanek;
                af[fm][0] = u2tf32(Ab[rbase]);
                af[fm][1] = u2tf32(Ab[rbase + 8 * PAD]);
                af[fm][2] = u2tf32(Ab[rbase + 4]);
                af[fm][3] = u2tf32(Ab[rbase + 8 * PAD + 4]);
            }
            #pragma unroll
            for (int fn = 0; fn < 4; fn++) {
                int nbase = (warp_n * 32 + fn * 8 + lane4) * PAD + lanek;
                uint32_t bf[2];
                bf[0] = u2tf32(B1b[nbase]);
                bf[1] = u2tf32(B1b[nbase + 4]);
                #pragma unroll
                for (int fm = 0; fm < 2; fm++) mma8(acc1[fm][fn], af[fm], bf);
            }
        }
        issue(k0 + 2 * BK, (k0 / BK + 2) % STAGES);
        st = (st + 1 == STAGES) ? 0 : st + 1;
    }

    #pragma unroll
    for (int fm = 0; fm < 2; fm++) {
        #pragma unroll
        for (int half = 0; half < 2; half++) {
            int mi = warp_m * 32 + fm * 16 + half * 8 + lane4;
            int m  = m0 + mi;
            if (m >= cnt) continue;
            size_t crow = routed ? (size_t)(base + m) : (size_t)m;
            float* cp = C + crow * DIMC + n0 + warp_n * 32 + lanek * 2;
            #pragma unroll
            for (int fn = 0; fn < 4; fn++) {
                float2 o;
                o.x = acc1[fm][fn][half * 2 + 0];
                o.y = acc1[fm][fn][half * 2 + 1];
                *(float2*)(cp + fn * 8) = o;
            }
        }
    }
}

__global__ __launch_bounds__(256) void combine_kernel(float* __restrict__ out) {
    int t = blockIdx.x;
    float w0 = g_pair_w[t*2+0], w1 = g_pair_w[t*2+1];
    size_t s0 = (size_t)g_slot_of_pair[t*2+0] * DIMC;
    size_t s1 = (size_t)g_slot_of_pair[t*2+1] * DIMC;
    int d = threadIdx.x * 4;
    float4 o  = *(float4*)(out + (size_t)t * DIMC + d);
    float4 r0 = *(const float4*)(g_rout + s0 + d);
    float4 r1 = *(const float4*)(g_rout + s1 + d);
    o.x += w0 * r0.x + w1 * r1.x;
    o.y += w0 * r0.y + w1 * r1.y;
    o.z += w0 * r0.z + w1 * r1.z;
    o.w += w0 * r0.w + w1 * r1.w;
    *(float4*)(out + (size_t)t * DIMC + d) = o;
}

// ---------------------------------------------------------------------------
extern "C" void kernel_launch(void* const* d_in, const int* in_sizes, int n_in,
                              void* d_out, int out_size) {
    const float* x      = (const float*)d_in[0];
    const float* gate_w = (const float*)d_in[1];
    const float* w1     = (const float*)d_in[2];
    const float* w2     = (const float*)d_in[3];
    const float* w3     = (const float*)d_in[4];
    const float* sw1    = (const float*)d_in[5];
    const float* sw2    = (const float*)d_in[6];
    const float* sw3    = (const float*)d_in[7];
    float* out = (float*)d_out;

    cudaFuncSetAttribute(swiglu_gemm, cudaFuncAttributeMaxDynamicSharedMemorySize, SMEM_DUAL);
    cudaFuncSetAttribute(down_gemm,   cudaFuncAttributeMaxDynamicSharedMemorySize, SMEM_SNGL);

    reset_kernel<<<1, 32>>>();
    gate_kernel<<<T, 128>>>(x, gate_w);
    scatter_kernel<<<1, 1024>>>();

    // merged SwiGLU: z in [0,16); z==16 -> shared
    swiglu_gemm<<<dim3(T / BM, SI / BN, E + 1), 256, SMEM_DUAL>>>(x, w1, w3, sw1, sw3);
    // merged down
    down_gemm<<<dim3(T / BM, DIMC / BN, E + 1), 256, SMEM_SNGL>>>(w2, sw2, out);

    combine_kernel<<<T, 256>>>(out);
}

// round 11
// speedup vs baseline: 1.2179x; 1.1364x over previous
#include <cuda_runtime.h>
#include <cstdint>
#include <math.h>

// ---------------------------------------------------------------------------
// MoE, tf32 mma.sync + cp.async 3-stage pipeline, k-permuted LDS.64 fragments.
//   gate (no atomics) -> scatter (histogram + offsets + scatter, 1 block)
//   swiglu_gemm merged: z<16 routed SwiGLU (gather) -> g_h ; z==16 shared -> g_hs
//   down_gemm merged:   z<16 routed down -> g_rout  ; z==16 shared down -> d_out
//   combine
// Fragment k-permutation: within each 8-k MMA group, thread lanek holds
// phys k = {2*lanek, 2*lanek+1} for BOTH A and B -> every fragment load is one
// ld.shared.v2.u32 from a row-major tile (16 floats/row, XOR-16B swizzle).
// ---------------------------------------------------------------------------

namespace {
constexpr int T     = 2048;
constexpr int DIMC  = 1024;
constexpr int E     = 16;
constexpr int NP    = T * 2;
constexpr int INTER = 512;
constexpr int SI    = 1024;

constexpr int BK = 16;
constexpr int STAGES = 3;
// swiglu: BM=64, BN=128 (dual)
constexpr int SW_ASTG = 64 * 64;     // bytes/stage (64 rows x 64B)
constexpr int SW_BSTG = 128 * 64;
constexpr int SMEM_SW = STAGES * (SW_ASTG + 2 * SW_BSTG);   // 61440
// down: BM=128, BN=128 (single)
constexpr int DN_ASTG = 128 * 64;
constexpr int DN_BSTG = 128 * 64;
constexpr int SMEM_DN = STAGES * (DN_ASTG + DN_BSTG);       // 49152
}

__device__ int   g_count[E];
__device__ int   g_offset[E];
__device__ int   g_pair_e[NP];
__device__ float g_pair_w[NP];
__device__ int   g_slot_of_pair[NP];
__device__ int   g_tok_of_slot[NP];
__device__ __align__(16) float g_h[(size_t)NP * INTER];
__device__ __align__(16) float g_rout[(size_t)NP * DIMC];
__device__ __align__(16) float g_hs[(size_t)T * SI];

// ---------------- helpers ----------------
__device__ __forceinline__ uint32_t u2tf32(uint32_t u) {
    uint32_t r;
    asm("cvt.rna.tf32.f32 %0, %1;" : "=r"(r) : "f"(__uint_as_float(u)));
    return r;
}
__device__ __forceinline__ uint32_t smem_u32(const void* p) {
    uint32_t a;
    asm("{ .reg .u64 t; cvta.to.shared.u64 t, %1; cvt.u32.u64 %0, t; }" : "=r"(a) : "l"(p));
    return a;
}
__device__ __forceinline__ void mma8(float* c, const uint32_t* a, const uint32_t* b) {
    asm volatile(
        "mma.sync.aligned.m16n8k8.row.col.f32.tf32.tf32.f32 "
        "{%0,%1,%2,%3},{%4,%5,%6,%7},{%8,%9},{%0,%1,%2,%3};"
        : "+f"(c[0]), "+f"(c[1]), "+f"(c[2]), "+f"(c[3])
        : "r"(a[0]), "r"(a[1]), "r"(a[2]), "r"(a[3]), "r"(b[0]), "r"(b[1]));
}
#define LDS64(r0, r1, addr) \
    asm volatile("ld.shared.v2.u32 {%0,%1}, [%2];" : "=r"(r0), "=r"(r1) : "r"(addr))
#define CP_A16(dst, src) asm volatile("cp.async.ca.shared.global [%0], [%1], 16;" :: "r"(dst), "l"(src))
#define CP_COMMIT()      asm volatile("cp.async.commit_group;" ::: "memory")
#define CP_WAIT1()       asm volatile("cp.async.wait_group 1;" ::: "memory")

// byte offset of a fragment LDS.64 within a row-major tile (16 floats = 64B per
// row, 16B chunk swizzle: chunk' = chunk ^ (row&3)). phys k pair = 2*lanek,+1.
__device__ __forceinline__ uint32_t foff(int row, int ks, int lanek) {
    int chunk = (ks << 1) + (lanek >> 1);
    return (uint32_t)(row * 64 + ((chunk ^ (row & 3)) << 4) + ((lanek & 1) << 3));
}
// byte offset of a 16B store chunk (cp.async dst)
__device__ __forceinline__ uint32_t soff(int row, int c) {
    return (uint32_t)(row * 64 + ((c ^ (row & 3)) << 4));
}

// ---------------- routing ----------------
__global__ __launch_bounds__(128) void gate_kernel(const float* __restrict__ x,
                                                   const float* __restrict__ gw) {
    __shared__ float xs[DIMC];
    __shared__ float part[8][E];
    __shared__ float logit[E];
    int t = blockIdx.x;
    for (int i = threadIdx.x; i < DIMC; i += 128) xs[i] = x[(size_t)t * DIMC + i];
    __syncthreads();
    int e = threadIdx.x & 15, chunk = threadIdx.x >> 4;
    const float* gr = gw + (size_t)e * DIMC + chunk * 128;
    const float* xr = xs + chunk * 128;
    float a0 = 0.f, a1 = 0.f, a2 = 0.f, a3 = 0.f;
    #pragma unroll 8
    for (int i = 0; i < 128; i += 4) {
        a0 += xr[i+0] * gr[i+0]; a1 += xr[i+1] * gr[i+1];
        a2 += xr[i+2] * gr[i+2]; a3 += xr[i+3] * gr[i+3];
    }
    part[chunk][e] = (a0 + a1) + (a2 + a3);
    __syncthreads();
    if (threadIdx.x < E) {
        float s = 0.f;
        #pragma unroll
        for (int c = 0; c < 8; c++) s += part[c][threadIdx.x];
        logit[threadIdx.x] = s;
    }
    __syncthreads();
    if (threadIdx.x == 0) {
        int i0 = 0; float v0 = logit[0];
        #pragma unroll
        for (int i = 1; i < E; i++) if (logit[i] > v0) { v0 = logit[i]; i0 = i; }
        int i1 = -1; float v1 = -1e30f;
        #pragma unroll
        for (int i = 0; i < E; i++) if (i != i0 && logit[i] > v1) { v1 = logit[i]; i1 = i; }
        float s0 = 1.f / (1.f + expf(-v0));
        float s1 = 1.f / (1.f + expf(-v1));
        float inv = 1.f / (s0 + s1);
        g_pair_e[t*2+0] = i0; g_pair_w[t*2+0] = s0 * inv;
        g_pair_e[t*2+1] = i1; g_pair_w[t*2+1] = s1 * inv;
    }
}

// histogram + offsets + scatter, one block
__global__ __launch_bounds__(1024) void scatter_kernel() {
    __shared__ int cnt[E], off[E], fill[E];
    if (threadIdx.x < E) { cnt[threadIdx.x] = 0; fill[threadIdx.x] = 0; }
    __syncthreads();
    for (int p = threadIdx.x; p < NP; p += 1024)
        atomicAdd(&cnt[g_pair_e[p]], 1);
    __syncthreads();
    if (threadIdx.x == 0) {
        int s = 0;
        #pragma unroll
        for (int e = 0; e < E; e++) {
            off[e] = s; g_offset[e] = s; g_count[e] = cnt[e]; s += cnt[e];
        }
    }
    __syncthreads();
    for (int p = threadIdx.x; p < NP; p += 1024) {
        int e = g_pair_e[p];
        int slot = off[e] + atomicAdd(&fill[e], 1);
        g_slot_of_pair[p] = slot;
        g_tok_of_slot[slot] = p >> 1;
    }
}

// ---------------------------------------------------------------------------
// SwiGLU GEMM: BM=64, BN=128, dual-B. z<16 routed (gather), z==16 shared.
// ---------------------------------------------------------------------------
__global__ __launch_bounds__(256, 2) void swiglu_gemm(const float* __restrict__ x,
                                                      const float* __restrict__ w1,
                                                      const float* __restrict__ w3,
                                                      const float* __restrict__ sw1,
                                                      const float* __restrict__ sw3) {
    extern __shared__ uint32_t sm[];
    __shared__ int rowsS[64];

    const int z       = blockIdx.z;
    const bool routed = (z < E);
    const int  Ntot   = routed ? INTER : SI;
    if (blockIdx.y * 128 >= Ntot) return;
    const int cnt  = routed ? g_count[z] : T;
    const int m0   = blockIdx.x * 64;
    if (m0 >= cnt) return;
    const int n0   = blockIdx.y * 128;
    const int base = routed ? g_offset[z] : 0;

    const float* B1 = routed ? (w1 + (size_t)z * INTER * DIMC) : sw1;
    const float* B3 = routed ? (w3 + (size_t)z * INTER * DIMC) : sw3;
    float* C = routed ? g_h : g_hs;

    const int tid    = threadIdx.x;
    const int wid    = tid >> 5;
    const int lane   = tid & 31;
    const int lane4  = lane >> 2;
    const int lanek  = lane & 3;
    const int warp_m = wid & 1;
    const int warp_n = wid >> 1;

    if (tid < 64) {
        int m = m0 + tid;
        rowsS[tid] = routed ? g_tok_of_slot[base + min(m, cnt - 1)]
                            : min(m, cnt - 1);
    }
    __syncthreads();

    const uint32_t smA = smem_u32(sm);
    const uint32_t smB = smA + STAGES * SW_ASTG;
    const uint32_t smC = smB + STAGES * SW_BSTG;

    // cp.async slots: A 1 chunk, B 2, C 2 per thread
    const int ar = tid >> 2, ac = tid & 3;
    const int br0 = ar, br1 = 64 + ar;
    const float* asrc  = x  + (size_t)rowsS[ar] * DIMC + ac * 4;
    const float* b1s0  = B1 + (size_t)(n0 + br0) * DIMC + ac * 4;
    const float* b1s1  = B1 + (size_t)(n0 + br1) * DIMC + ac * 4;
    const float* b3s0  = B3 + (size_t)(n0 + br0) * DIMC + ac * 4;
    const float* b3s1  = B3 + (size_t)(n0 + br1) * DIMC + ac * 4;
    const uint32_t adst  = smA + soff(ar, ac);
    const uint32_t bdst0 = smB + soff(br0, ac);
    const uint32_t bdst1 = smB + soff(br1, ac);
    const uint32_t cdst0 = smC + soff(br0, ac);
    const uint32_t cdst1 = smC + soff(br1, ac);

    auto issue = [&](int k0, int st) {
        if (k0 < DIMC) {
            CP_A16(adst  + st * SW_ASTG, asrc + k0);
            CP_A16(bdst0 + st * SW_BSTG, b1s0 + k0);
            CP_A16(bdst1 + st * SW_BSTG, b1s1 + k0);
            CP_A16(cdst0 + st * SW_BSTG, b3s0 + k0);
            CP_A16(cdst1 + st * SW_BSTG, b3s1 + k0);
        }
        CP_COMMIT();
    };

    issue(0, 0);
    issue(BK, 1);

    float acc1[2][4][4] = {};
    float acc3[2][4][4] = {};

    int st = 0;
    for (int k0 = 0; k0 < DIMC; k0 += BK) {
        CP_WAIT1();
        __syncthreads();
        const uint32_t aSt = smA + st * SW_ASTG;
        const uint32_t bSt = smB + st * SW_BSTG;
        const uint32_t cSt = smC + st * SW_BSTG;

        #pragma unroll
        for (int ks = 0; ks < 2; ks++) {
            uint32_t af[2][4];
            #pragma unroll
            for (int fm = 0; fm < 2; fm++) {
                int row = warp_m * 32 + fm * 16 + lane4;
                uint32_t ad = aSt + foff(row, ks, lanek);
                LDS64(af[fm][0], af[fm][2], ad);
                LDS64(af[fm][1], af[fm][3], ad + 8 * 64);
                af[fm][0] = u2tf32(af[fm][0]); af[fm][1] = u2tf32(af[fm][1]);
                af[fm][2] = u2tf32(af[fm][2]); af[fm][3] = u2tf32(af[fm][3]);
            }
            #pragma unroll
            for (int fn = 0; fn < 4; fn++) {
                int rowb = warp_n * 32 + fn * 8 + lane4;
                uint32_t off = foff(rowb, ks, lanek);
                uint32_t bf[2], cf[2];
                LDS64(bf[0], bf[1], bSt + off);
                LDS64(cf[0], cf[1], cSt + off);
                bf[0] = u2tf32(bf[0]); bf[1] = u2tf32(bf[1]);
                cf[0] = u2tf32(cf[0]); cf[1] = u2tf32(cf[1]);
                mma8(acc1[0][fn], af[0], bf);
                mma8(acc1[1][fn], af[1], bf);
                mma8(acc3[0][fn], af[0], cf);
                mma8(acc3[1][fn], af[1], cf);
            }
        }
        issue(k0 + 2 * BK, (k0 / BK + 2) % STAGES);
        st = (st + 1 == STAGES) ? 0 : st + 1;
    }

    #pragma unroll
    for (int fm = 0; fm < 2; fm++) {
        #pragma unroll
        for (int half = 0; half < 2; half++) {
            int mi = warp_m * 32 + fm * 16 + half * 8 + lane4;
            int m  = m0 + mi;
            if (m >= cnt) continue;
            size_t crow = routed ? (size_t)(base + m) : (size_t)m;
            float* cp = C + crow * Ntot + n0 + warp_n * 32 + lanek * 2;
            #pragma unroll
            for (int fn = 0; fn < 4; fn++) {
                float v0 = acc1[fm][fn][half * 2 + 0];
                float v1 = acc1[fm][fn][half * 2 + 1];
                float2 o;
                o.x = (v0 / (1.f + __expf(-v0))) * acc3[fm][fn][half * 2 + 0];
                o.y = (v1 / (1.f + __expf(-v1))) * acc3[fm][fn][half * 2 + 1];
                *(float2*)(cp + fn * 8) = o;
            }
        }
    }
}

// ---------------------------------------------------------------------------
// Down GEMM: BM=128, BN=128, single-B, warp tile 64x32 (fm=4).
// z<16 routed (A=g_h, KD=512) -> g_rout ; z==16 shared (A=g_hs, KD=1024) -> out.
// ---------------------------------------------------------------------------
__global__ __launch_bounds__(256, 2) void down_gemm(const float* __restrict__ w2,
                                                    const float* __restrict__ sw2,
                                                    float* __restrict__ out) {
    extern __shared__ uint32_t sm[];
    __shared__ int rowsS[128];

    const int z       = blockIdx.z;
    const bool routed = (z < E);
    const int  KD     = routed ? INTER : SI;
    const int cnt  = routed ? g_count[z] : T;
    const int m0   = blockIdx.x * 128;
    if (m0 >= cnt) return;
    const int n0   = blockIdx.y * 128;
    const int base = routed ? g_offset[z] : 0;

    const float* A  = routed ? g_h : g_hs;
    const float* B1 = routed ? (w2 + (size_t)z * DIMC * INTER) : sw2;
    float* C = routed ? g_rout : out;

    const int tid    = threadIdx.x;
    const int wid    = tid >> 5;
    const int lane   = tid & 31;
    const int lane4  = lane >> 2;
    const int lanek  = lane & 3;
    const int warp_m = wid & 1;
    const int warp_n = wid >> 1;

    if (tid < 128) {
        int m = m0 + min(tid, cnt - 1 - m0 >= 0 ? (cnt - 1 - m0 < 127 ? cnt - 1 - m0 : 127) : 0);
        // simpler: clamp
        int mm = m0 + tid; if (mm >= cnt) mm = cnt - 1;
        rowsS[tid] = routed ? (base + mm) : mm;
    }
    __syncthreads();

    const uint32_t smA = smem_u32(sm);
    const uint32_t smB = smA + STAGES * DN_ASTG;

    const int ar0 = tid >> 2, ar1 = 64 + (tid >> 2), ac = tid & 3;
    const float* asrc0 = A  + (size_t)rowsS[ar0] * KD + ac * 4;
    const float* asrc1 = A  + (size_t)rowsS[ar1] * KD + ac * 4;
    const float* bsrc0 = B1 + (size_t)(n0 + ar0) * KD + ac * 4;
    const float* bsrc1 = B1 + (size_t)(n0 + ar1) * KD + ac * 4;
    const uint32_t adst0 = smA + soff(ar0, ac);
    const uint32_t adst1 = smA + soff(ar1, ac);
    const uint32_t bdst0 = smB + soff(ar0, ac);
    const uint32_t bdst1 = smB + soff(ar1, ac);

    auto issue = [&](int k0, int st) {
        if (k0 < KD) {
            CP_A16(adst0 + st * DN_ASTG, asrc0 + k0);
            CP_A16(adst1 + st * DN_ASTG, asrc1 + k0);
            CP_A16(bdst0 + st * DN_BSTG, bsrc0 + k0);
            CP_A16(bdst1 + st * DN_BSTG, bsrc1 + k0);
        }
        CP_COMMIT();
    };

    issue(0, 0);
    issue(BK, 1);

    float acc[4][4][4] = {};

    int st = 0;
    for (int k0 = 0; k0 < KD; k0 += BK) {
        CP_WAIT1();
        __syncthreads();
        const uint32_t aSt = smA + st * DN_ASTG;
        const uint32_t bSt = smB + st * DN_BSTG;

        #pragma unroll
        for (int ks = 0; ks < 2; ks++) {
            uint32_t af[4][4];
            #pragma unroll
            for (int fm = 0; fm < 4; fm++) {
                int row = warp_m * 64 + fm * 16 + lane4;
                uint32_t ad = aSt + foff(row, ks, lanek);
                LDS64(af[fm][0], af[fm][2], ad);
                LDS64(af[fm][1], af[fm][3], ad + 8 * 64);
                af[fm][0] = u2tf32(af[fm][0]); af[fm][1] = u2tf32(af[fm][1]);
                af[fm][2] = u2tf32(af[fm][2]); af[fm][3] = u2tf32(af[fm][3]);
            }
            #pragma unroll
            for (int fn = 0; fn < 4; fn++) {
                int rowb = warp_n * 32 + fn * 8 + lane4;
                uint32_t bf[2];
                LDS64(bf[0], bf[1], bSt + foff(rowb, ks, lanek));
                bf[0] = u2tf32(bf[0]); bf[1] = u2tf32(bf[1]);
                #pragma unroll
                for (int fm = 0; fm < 4; fm++) mma8(acc[fm][fn], af[fm], bf);
            }
        }
        issue(k0 + 2 * BK, (k0 / BK + 2) % STAGES);
        st = (st + 1 == STAGES) ? 0 : st + 1;
    }

    #pragma unroll
    for (int fm = 0; fm < 4; fm++) {
        #pragma unroll
        for (int half = 0; half < 2; half++) {
            int mi = warp_m * 64 + fm * 16 + half * 8 + lane4;
            int m  = m0 + mi;
            if (m >= cnt) continue;
            size_t crow = routed ? (size_t)(base + m) : (size_t)m;
            float* cp = C + crow * DIMC + n0 + warp_n * 32 + lanek * 2;
            #pragma unroll
            for (int fn = 0; fn < 4; fn++) {
                float2 o;
                o.x = acc[fm][fn][half * 2 + 0];
                o.y = acc[fm][fn][half * 2 + 1];
                *(float2*)(cp + fn * 8) = o;
            }
        }
    }
}

__global__ __launch_bounds__(256) void combine_kernel(float* __restrict__ out) {
    int t = blockIdx.x;
    float w0 = g_pair_w[t*2+0], w1 = g_pair_w[t*2+1];
    size_t s0 = (size_t)g_slot_of_pair[t*2+0] * DIMC;
    size_t s1 = (size_t)g_slot_of_pair[t*2+1] * DIMC;
    int d = threadIdx.x * 4;
    float4 o  = *(float4*)(out + (size_t)t * DIMC + d);
    float4 r0 = *(const float4*)(g_rout + s0 + d);
    float4 r1 = *(const float4*)(g_rout + s1 + d);
    o.x += w0 * r0.x + w1 * r1.x;
    o.y += w0 * r0.y + w1 * r1.y;
    o.z += w0 * r0.z + w1 * r1.z;
    o.w += w0 * r0.w + w1 * r1.w;
    *(float4*)(out + (size_t)t * DIMC + d) = o;
}

// ---------------------------------------------------------------------------
extern "C" void kernel_launch(void* const* d_in, const int* in_sizes, int n_in,
                              void* d_out, int out_size) {
    const float* x      = (const float*)d_in[0];
    const float* gate_w = (const float*)d_in[1];
    const float* w1     = (const float*)d_in[2];
    const float* w2     = (const float*)d_in[3];
    const float* w3     = (const float*)d_in[4];
    const float* sw1    = (const float*)d_in[5];
    const float* sw2    = (const float*)d_in[6];
    const float* sw3    = (const float*)d_in[7];
    float* out = (float*)d_out;

    cudaFuncSetAttribute(swiglu_gemm, cudaFuncAttributeMaxDynamicSharedMemorySize, SMEM_SW);
    cudaFuncSetAttribute(down_gemm,   cudaFuncAttributeMaxDynamicSharedMemorySize, SMEM_DN);

    gate_kernel<<<T, 128>>>(x, gate_w);
    scatter_kernel<<<1, 1024>>>();

    swiglu_gemm<<<dim3(T / 64, SI / 128, E + 1), 256, SMEM_SW>>>(x, w1, w3, sw1, sw3);
    down_gemm<<<dim3(T / 128, DIMC / 128, E + 1), 256, SMEM_DN>>>(w2, sw2, out);

    combine_kernel<<<T, 256>>>(out);
}

// round 12
// speedup vs baseline: 1.2505x; 1.0268x over previous
#include <cuda_runtime.h>
#include <cstdint>
#include <math.h>

// ---------------------------------------------------------------------------
// MoE, tf32 mma.sync + cp.async 4-stage pipeline, k-permuted LDS.64 fragments.
//   gate: routing + writes tf32-rounded x copy (g_xr)
//   scatter: histogram + offsets + scatter (1 block)
//   swiglu_gemm merged: z<16 routed SwiGLU (gather) -> g_h ; z==16 -> g_hs
//       (A = g_xr pre-rounded: no cvt; epilogue stores tf32-rounded h)
//   down_gemm merged: z<16 routed -> g_rout ; z==16 shared -> d_out
//       (A = g_h/g_hs pre-rounded: no cvt; B keeps consume-time cvt)
//   combine
// ---------------------------------------------------------------------------

namespace {
constexpr int T     = 2048;
constexpr int DIMC  = 1024;
constexpr int E     = 16;
constexpr int NP    = T * 2;
constexpr int INTER = 512;
constexpr int SI    = 1024;

constexpr int BK = 16;
constexpr int STAGES = 4;
constexpr int SW_ASTG = 64 * 64;      // bytes/stage
constexpr int SW_BSTG = 128 * 64;
constexpr int SMEM_SW = STAGES * (SW_ASTG + 2 * SW_BSTG);   // 81920
constexpr int DN_ASTG = 128 * 64;
constexpr int DN_BSTG = 128 * 64;
constexpr int SMEM_DN = STAGES * (DN_ASTG + DN_BSTG);       // 65536

constexpr size_t NX = (size_t)T * DIMC;
}

__device__ int   g_count[E];
__device__ int   g_offset[E];
__device__ int   g_pair_e[NP];
__device__ float g_pair_w[NP];
__device__ int   g_slot_of_pair[NP];
__device__ int   g_tok_of_slot[NP];
__device__ __align__(16) float g_xr[NX];
__device__ __align__(16) float g_h[(size_t)NP * INTER];
__device__ __align__(16) float g_rout[(size_t)NP * DIMC];
__device__ __align__(16) float g_hs[(size_t)T * SI];

// ---------------- helpers ----------------
__device__ __forceinline__ uint32_t u2tf32(uint32_t u) {
    uint32_t r;
    asm("cvt.rna.tf32.f32 %0, %1;" : "=r"(r) : "f"(__uint_as_float(u)));
    return r;
}
__device__ __forceinline__ float f2tf32f(float f) {
    uint32_t r;
    asm("cvt.rna.tf32.f32 %0, %1;" : "=r"(r) : "f"(f));
    return __uint_as_float(r);
}
__device__ __forceinline__ uint32_t smem_u32(const void* p) {
    uint32_t a;
    asm("{ .reg .u64 t; cvta.to.shared.u64 t, %1; cvt.u32.u64 %0, t; }" : "=r"(a) : "l"(p));
    return a;
}
__device__ __forceinline__ void mma8(float* c, const uint32_t* a, const uint32_t* b) {
    asm volatile(
        "mma.sync.aligned.m16n8k8.row.col.f32.tf32.tf32.f32 "
        "{%0,%1,%2,%3},{%4,%5,%6,%7},{%8,%9},{%0,%1,%2,%3};"
        : "+f"(c[0]), "+f"(c[1]), "+f"(c[2]), "+f"(c[3])
        : "r"(a[0]), "r"(a[1]), "r"(a[2]), "r"(a[3]), "r"(b[0]), "r"(b[1]));
}
#define LDS64(r0, r1, addr) \
    asm volatile("ld.shared.v2.u32 {%0,%1}, [%2];" : "=r"(r0), "=r"(r1) : "r"(addr))
#define CP_A16(dst, src) asm volatile("cp.async.ca.shared.global [%0], [%1], 16;" :: "r"(dst), "l"(src))
#define CP_COMMIT()      asm volatile("cp.async.commit_group;" ::: "memory")
#define CP_WAIT2()       asm volatile("cp.async.wait_group 2;" ::: "memory")

// fragment LDS.64 offset in row-major tile (16 floats/row, XOR-16B swizzle)
__device__ __forceinline__ uint32_t foff(int row, int ks, int lanek) {
    int chunk = (ks << 1) + (lanek >> 1);
    return (uint32_t)(row * 64 + ((chunk ^ (row & 3)) << 4) + ((lanek & 1) << 3));
}
__device__ __forceinline__ uint32_t soff(int row, int c) {
    return (uint32_t)(row * 64 + ((c ^ (row & 3)) << 4));
}

// ---------------- routing (+ rounded x) ----------------
__global__ __launch_bounds__(128) void gate_kernel(const float* __restrict__ x,
                                                   const float* __restrict__ gw) {
    __shared__ float xs[DIMC];
    __shared__ float part[8][E];
    __shared__ float logit[E];
    int t = blockIdx.x;
    for (int i = threadIdx.x; i < DIMC; i += 128) xs[i] = x[(size_t)t * DIMC + i];
    __syncthreads();
    // rounded copy for GEMM A operand
    for (int i = threadIdx.x; i < DIMC; i += 128)
        g_xr[(size_t)t * DIMC + i] = f2tf32f(xs[i]);

    int e = threadIdx.x & 15, chunk = threadIdx.x >> 4;
    const float* gr = gw + (size_t)e * DIMC + chunk * 128;
    const float* xr = xs + chunk * 128;
    float a0 = 0.f, a1 = 0.f, a2 = 0.f, a3 = 0.f;
    #pragma unroll 8
    for (int i = 0; i < 128; i += 4) {
        a0 += xr[i+0] * gr[i+0]; a1 += xr[i+1] * gr[i+1];
        a2 += xr[i+2] * gr[i+2]; a3 += xr[i+3] * gr[i+3];
    }
    part[chunk][e] = (a0 + a1) + (a2 + a3);
    __syncthreads();
    if (threadIdx.x < E) {
        float s = 0.f;
        #pragma unroll
        for (int c = 0; c < 8; c++) s += part[c][threadIdx.x];
        logit[threadIdx.x] = s;
    }
    __syncthreads();
    if (threadIdx.x == 0) {
        int i0 = 0; float v0 = logit[0];
        #pragma unroll
        for (int i = 1; i < E; i++) if (logit[i] > v0) { v0 = logit[i]; i0 = i; }
        int i1 = -1; float v1 = -1e30f;
        #pragma unroll
        for (int i = 0; i < E; i++) if (i != i0 && logit[i] > v1) { v1 = logit[i]; i1 = i; }
        float s0 = 1.f / (1.f + expf(-v0));
        float s1 = 1.f / (1.f + expf(-v1));
        float inv = 1.f / (s0 + s1);
        g_pair_e[t*2+0] = i0; g_pair_w[t*2+0] = s0 * inv;
        g_pair_e[t*2+1] = i1; g_pair_w[t*2+1] = s1 * inv;
    }
}

__global__ __launch_bounds__(1024) void scatter_kernel() {
    __shared__ int cnt[E], off[E], fill[E];
    if (threadIdx.x < E) { cnt[threadIdx.x] = 0; fill[threadIdx.x] = 0; }
    __syncthreads();
    for (int p = threadIdx.x; p < NP; p += 1024)
        atomicAdd(&cnt[g_pair_e[p]], 1);
    __syncthreads();
    if (threadIdx.x == 0) {
        int s = 0;
        #pragma unroll
        for (int e = 0; e < E; e++) {
            off[e] = s; g_offset[e] = s; g_count[e] = cnt[e]; s += cnt[e];
        }
    }
    __syncthreads();
    for (int p = threadIdx.x; p < NP; p += 1024) {
        int e = g_pair_e[p];
        int slot = off[e] + atomicAdd(&fill[e], 1);
        g_slot_of_pair[p] = slot;
        g_tok_of_slot[slot] = p >> 1;
    }
}

// ---------------------------------------------------------------------------
// SwiGLU GEMM: BM=64, BN=128, dual-B. A = g_xr (pre-rounded, no cvt).
// ---------------------------------------------------------------------------
__global__ __launch_bounds__(256, 2) void swiglu_gemm(const float* __restrict__ w1,
                                                      const float* __restrict__ w3,
                                                      const float* __restrict__ sw1,
                                                      const float* __restrict__ sw3) {
    extern __shared__ uint32_t sm[];
    __shared__ int rowsS[64];

    const int z       = blockIdx.z;
    const bool routed = (z < E);
    const int  Ntot   = routed ? INTER : SI;
    if (blockIdx.y * 128 >= Ntot) return;
    const int cnt  = routed ? g_count[z] : T;
    const int m0   = blockIdx.x * 64;
    if (m0 >= cnt) return;
    const int n0   = blockIdx.y * 128;
    const int base = routed ? g_offset[z] : 0;

    const float* B1 = routed ? (w1 + (size_t)z * INTER * DIMC) : sw1;
    const float* B3 = routed ? (w3 + (size_t)z * INTER * DIMC) : sw3;
    float* C = routed ? g_h : g_hs;

    const int tid    = threadIdx.x;
    const int wid    = tid >> 5;
    const int lane   = tid & 31;
    const int lane4  = lane >> 2;
    const int lanek  = lane & 3;
    const int warp_m = wid & 1;
    const int warp_n = wid >> 1;

    if (tid < 64) {
        int m = m0 + tid;
        rowsS[tid] = routed ? g_tok_of_slot[base + min(m, cnt - 1)]
                            : min(m, cnt - 1);
    }
    __syncthreads();

    const uint32_t smA = smem_u32(sm);
    const uint32_t smB = smA + STAGES * SW_ASTG;
    const uint32_t smC = smB + STAGES * SW_BSTG;

    const int ar = tid >> 2, ac = tid & 3;
    const float* asrc = g_xr + (size_t)rowsS[ar] * DIMC + ac * 4;
    const float* b1s0 = B1 + (size_t)(n0 + ar) * DIMC + ac * 4;
    const float* b1s1 = B1 + (size_t)(n0 + 64 + ar) * DIMC + ac * 4;
    const float* b3s0 = B3 + (size_t)(n0 + ar) * DIMC + ac * 4;
    const float* b3s1 = B3 + (size_t)(n0 + 64 + ar) * DIMC + ac * 4;
    const uint32_t adst  = smA + soff(ar, ac);
    const uint32_t bdst0 = smB + soff(ar, ac);
    const uint32_t bdst1 = smB + soff(64 + ar, ac);
    const uint32_t cdst0 = smC + soff(ar, ac);
    const uint32_t cdst1 = smC + soff(64 + ar, ac);

    auto issue = [&](int k0, int st) {
        if (k0 < DIMC) {
            CP_A16(adst  + st * SW_ASTG, asrc + k0);
            CP_A16(bdst0 + st * SW_BSTG, b1s0 + k0);
            CP_A16(bdst1 + st * SW_BSTG, b1s1 + k0);
            CP_A16(cdst0 + st * SW_BSTG, b3s0 + k0);
            CP_A16(cdst1 + st * SW_BSTG, b3s1 + k0);
        }
        CP_COMMIT();
    };

    issue(0, 0); issue(BK, 1); issue(2 * BK, 2);

    float acc1[2][4][4] = {};
    float acc3[2][4][4] = {};

    int st = 0;
    for (int k0 = 0; k0 < DIMC; k0 += BK) {
        CP_WAIT2();
        __syncthreads();
        const uint32_t aSt = smA + st * SW_ASTG;
        const uint32_t bSt = smB + st * SW_BSTG;
        const uint32_t cSt = smC + st * SW_BSTG;

        #pragma unroll
        for (int ks = 0; ks < 2; ks++) {
            uint32_t af[2][4];
            #pragma unroll
            for (int fm = 0; fm < 2; fm++) {
                int row = warp_m * 32 + fm * 16 + lane4;
                uint32_t ad = aSt + foff(row, ks, lanek);
                LDS64(af[fm][0], af[fm][2], ad);
                LDS64(af[fm][1], af[fm][3], ad + 8 * 64);
            }
            #pragma unroll
            for (int fn = 0; fn < 4; fn++) {
                int rowb = warp_n * 32 + fn * 8 + lane4;
                uint32_t off = foff(rowb, ks, lanek);
                uint32_t bf[2], cf[2];
                LDS64(bf[0], bf[1], bSt + off);
                LDS64(cf[0], cf[1], cSt + off);
                bf[0] = u2tf32(bf[0]); bf[1] = u2tf32(bf[1]);
                cf[0] = u2tf32(cf[0]); cf[1] = u2tf32(cf[1]);
                mma8(acc1[0][fn], af[0], bf);
                mma8(acc1[1][fn], af[1], bf);
                mma8(acc3[0][fn], af[0], cf);
                mma8(acc3[1][fn], af[1], cf);
            }
        }
        issue(k0 + 3 * BK, (k0 / BK + 3) & (STAGES - 1));
        st = (st + 1) & (STAGES - 1);
    }

    // epilogue: SwiGLU, store tf32-rounded (down_gemm reads without cvt)
    #pragma unroll
    for (int fm = 0; fm < 2; fm++) {
        #pragma unroll
        for (int half = 0; half < 2; half++) {
            int mi = warp_m * 32 + fm * 16 + half * 8 + lane4;
            int m  = m0 + mi;
            if (m >= cnt) continue;
            size_t crow = routed ? (size_t)(base + m) : (size_t)m;
            float* cp = C + crow * Ntot + n0 + warp_n * 32 + lanek * 2;
            #pragma unroll
            for (int fn = 0; fn < 4; fn++) {
                float v0 = acc1[fm][fn][half * 2 + 0];
                float v1 = acc1[fm][fn][half * 2 + 1];
                float2 o;
                o.x = f2tf32f((v0 / (1.f + __expf(-v0))) * acc3[fm][fn][half * 2 + 0]);
                o.y = f2tf32f((v1 / (1.f + __expf(-v1))) * acc3[fm][fn][half * 2 + 1]);
                *(float2*)(cp + fn * 8) = o;
            }
        }
    }
}

// ---------------------------------------------------------------------------
// Down GEMM: BM=128, BN=128, warp 64x32. A pre-rounded (no cvt).
// ---------------------------------------------------------------------------
__global__ __launch_bounds__(256, 2) void down_gemm(const float* __restrict__ w2,
                                                    const float* __restrict__ sw2,
                                                    float* __restrict__ out) {
    extern __shared__ uint32_t sm[];
    __shared__ int rowsS[128];

    const int z       = blockIdx.z;
    const bool routed = (z < E);
    const int  KD     = routed ? INTER : SI;
    const int cnt  = routed ? g_count[z] : T;
    const int m0   = blockIdx.x * 128;
    if (m0 >= cnt) return;
    const int n0   = blockIdx.y * 128;
    const int base = routed ? g_offset[z] : 0;

    const float* A  = routed ? g_h : g_hs;
    const float* B1 = routed ? (w2 + (size_t)z * DIMC * INTER) : sw2;
    float* C = routed ? g_rout : out;

    const int tid    = threadIdx.x;
    const int wid    = tid >> 5;
    const int lane   = tid & 31;
    const int lane4  = lane >> 2;
    const int lanek  = lane & 3;
    const int warp_m = wid & 1;
    const int warp_n = wid >> 1;

    if (tid < 128) {
        int mm = m0 + tid;
        if (mm >= cnt) mm = cnt - 1;
        rowsS[tid] = routed ? (base + mm) : mm;
    }
    __syncthreads();

    const uint32_t smA = smem_u32(sm);
    const uint32_t smB = smA + STAGES * DN_ASTG;

    const int ar0 = tid >> 2, ar1 = 64 + (tid >> 2), ac = tid & 3;
    const float* asrc0 = A  + (size_t)rowsS[ar0] * KD + ac * 4;
    const float* asrc1 = A  + (size_t)rowsS[ar1] * KD + ac * 4;
    const float* bsrc0 = B1 + (size_t)(n0 + ar0) * KD + ac * 4;
    const float* bsrc1 = B1 + (size_t)(n0 + ar1) * KD + ac * 4;
    const uint32_t adst0 = smA + soff(ar0, ac);
    const uint32_t adst1 = smA + soff(ar1, ac);
    const uint32_t bdst0 = smB + soff(ar0, ac);
    const uint32_t bdst1 = smB + soff(ar1, ac);

    auto issue = [&](int k0, int st) {
        if (k0 < KD) {
            CP_A16(adst0 + st * DN_ASTG, asrc0 + k0);
            CP_A16(adst1 + st * DN_ASTG, asrc1 + k0);
            CP_A16(bdst0 + st * DN_BSTG, bsrc0 + k0);
            CP_A16(bdst1 + st * DN_BSTG, bsrc1 + k0);
        }
        CP_COMMIT();
    };

    issue(0, 0); issue(BK, 1); issue(2 * BK, 2);

    float acc[4][4][4] = {};

    int st = 0;
    for (int k0 = 0; k0 < KD; k0 += BK) {
        CP_WAIT2();
        __syncthreads();
        const uint32_t aSt = smA + st * DN_ASTG;
        const uint32_t bSt = smB + st * DN_BSTG;

        #pragma unroll
        for (int ks = 0; ks < 2; ks++) {
            uint32_t af[4][4];
            #pragma unroll
            for (int fm = 0; fm < 4; fm++) {
                int row = warp_m * 64 + fm * 16 + lane4;
                uint32_t ad = aSt + foff(row, ks, lanek);
                LDS64(af[fm][0], af[fm][2], ad);
                LDS64(af[fm][1], af[fm][3], ad + 8 * 64);
            }
            #pragma unroll
            for (int fn = 0; fn < 4; fn++) {
                int rowb = warp_n * 32 + fn * 8 + lane4;
                uint32_t bf[2];
                LDS64(bf[0], bf[1], bSt + foff(rowb, ks, lanek));
                bf[0] = u2tf32(bf[0]); bf[1] = u2tf32(bf[1]);
                #pragma unroll
                for (int fm = 0; fm < 4; fm++) mma8(acc[fm][fn], af[fm], bf);
            }
        }
        issue(k0 + 3 * BK, (k0 / BK + 3) & (STAGES - 1));
        st = (st + 1) & (STAGES - 1);
    }

    #pragma unroll
    for (int fm = 0; fm < 4; fm++) {
        #pragma unroll
        for (int half = 0; half < 2; half++) {
            int mi = warp_m * 64 + fm * 16 + half * 8 + lane4;
            int m  = m0 + mi;
            if (m >= cnt) continue;
            size_t crow = routed ? (size_t)(base + m) : (size_t)m;
            float* cp = C + crow * DIMC + n0 + warp_n * 32 + lanek * 2;
            #pragma unroll
            for (int fn = 0; fn < 4; fn++) {
                float2 o;
                o.x = acc[fm][fn][half * 2 + 0];
                o.y = acc[fm][fn][half * 2 + 1];
                *(float2*)(cp + fn * 8) = o;
            }
        }
    }
}

__global__ __launch_bounds__(256) void combine_kernel(float* __restrict__ out) {
    int t = blockIdx.x;
    float w0 = g_pair_w[t*2+0], w1 = g_pair_w[t*2+1];
    size_t s0 = (size_t)g_slot_of_pair[t*2+0] * DIMC;
    size_t s1 = (size_t)g_slot_of_pair[t*2+1] * DIMC;
    int d = threadIdx.x * 4;
    float4 o  = *(float4*)(out + (size_t)t * DIMC + d);
    float4 r0 = *(const float4*)(g_rout + s0 + d);
    float4 r1 = *(const float4*)(g_rout + s1 + d);
    o.x += w0 * r0.x + w1 * r1.x;
    o.y += w0 * r0.y + w1 * r1.y;
    o.z += w0 * r0.z + w1 * r1.z;
    o.w += w0 * r0.w + w1 * r1.w;
    *(float4*)(out + (size_t)t * DIMC + d) = o;
}

// ---------------------------------------------------------------------------
extern "C" void kernel_launch(void* const* d_in, const int* in_sizes, int n_in,
                              void* d_out, int out_size) {
    const float* x      = (const float*)d_in[0];
    const float* gate_w = (const float*)d_in[1];
    const float* w1     = (const float*)d_in[2];
    const float* w2     = (const float*)d_in[3];
    const float* w3     = (const float*)d_in[4];
    const float* sw1    = (const float*)d_in[5];
    const float* sw2    = (const float*)d_in[6];
    const float* sw3    = (const float*)d_in[7];
    float* out = (float*)d_out;

    cudaFuncSetAttribute(swiglu_gemm, cudaFuncAttributeMaxDynamicSharedMemorySize, SMEM_SW);
    cudaFuncSetAttribute(down_gemm,   cudaFuncAttributeMaxDynamicSharedMemorySize, SMEM_DN);

    gate_kernel<<<T, 128>>>(x, gate_w);
    scatter_kernel<<<1, 1024>>>();

    swiglu_gemm<<<dim3(T / 64, SI / 128, E + 1), 256, SMEM_SW>>>(w1, w3, sw1, sw3);
    down_gemm<<<dim3(T / 128, DIMC / 128, E + 1), 256, SMEM_DN>>>(w2, sw2, out);

    combine_kernel<<<T, 256>>>(out);
}

// round 13
// speedup vs baseline: 1.5241x; 1.2188x over previous
#include <cuda_runtime.h>
#include <cuda_fp16.h>
#include <cstdint>
#include <math.h>

// ---------------------------------------------------------------------------
// MoE via fp16 mma.sync m16n8k16 (same 10-bit mantissa as tf32, 2x rate,
// half the bytes), cp.async 4-stage pipeline, k-permuted LDS.64 fragments.
//   convert: weights -> k-permuted fp16 (once, ~60MB out)
//   gate: routing + k-permuted fp16 x copy
//   scatter: histogram + offsets + scatter (1 block)
//   swiglu_gemm merged: z<16 routed (gather) -> g_h(fp16,perm) ; z==16 -> g_hs
//   down_gemm merged:   z<16 routed -> g_rout(fp32) ; z==16 shared -> d_out
//   combine
// k-permutation within each 16-k group: pos(k) = (k&1) + 4*((k>>1)&3) + 2*((k>>3)&1)
// => fragment pairs {a0,a2}/{a1,a3}/{b0,b1} are 8B-contiguous -> one LDS.64.
// ---------------------------------------------------------------------------

namespace {
constexpr int T     = 2048;
constexpr int DIMC  = 1024;
constexpr int E     = 16;
constexpr int NP    = T * 2;
constexpr int INTER = 512;
constexpr int SI    = 1024;

constexpr int BK = 32;               // halves per stage (2 k16 groups)
constexpr int STAGES = 4;
constexpr int SW_ASTG = 64 * 64;     // bytes/stage: 64 rows x 64B(32 halves)
constexpr int SW_BSTG = 128 * 64;
constexpr int SMEM_SW = STAGES * (SW_ASTG + 2 * SW_BSTG);   // 81920
constexpr int DN_ASTG = 128 * 64;
constexpr int DN_BSTG = 128 * 64;
constexpr int SMEM_DN = STAGES * (DN_ASTG + DN_BSTG);       // 65536

constexpr size_t NX = (size_t)T * DIMC;
constexpr size_t NW = (size_t)E * INTER * DIMC;
constexpr size_t NS = (size_t)SI * DIMC;
constexpr size_t GW = NW / 16;
constexpr size_t GS = NS / 16;
}

__device__ int   g_count[E];
__device__ int   g_offset[E];
__device__ int   g_pair_e[NP];
__device__ float g_pair_w[NP];
__device__ int   g_slot_of_pair[NP];
__device__ int   g_tok_of_slot[NP];
__device__ __align__(16) __half g_xh[NX];
__device__ __align__(16) __half g_w1h[NW];
__device__ __align__(16) __half g_w2h[NW];
__device__ __align__(16) __half g_w3h[NW];
__device__ __align__(16) __half g_sw1h[NS];
__device__ __align__(16) __half g_sw2h[NS];
__device__ __align__(16) __half g_sw3h[NS];
__device__ __align__(16) __half g_h[(size_t)NP * INTER];
__device__ __align__(16) __half g_hs[(size_t)T * SI];
__device__ __align__(16) float  g_rout[(size_t)NP * DIMC];

// ---------------- helpers ----------------
__device__ __forceinline__ uint32_t smem_u32(const void* p) {
    uint32_t a;
    asm("{ .reg .u64 t; cvta.to.shared.u64 t, %1; cvt.u32.u64 %0, t; }" : "=r"(a) : "l"(p));
    return a;
}
__device__ __forceinline__ void mma16(float* c, const uint32_t* a, const uint32_t* b) {
    asm volatile(
        "mma.sync.aligned.m16n8k16.row.col.f32.f16.f16.f32 "
        "{%0,%1,%2,%3},{%4,%5,%6,%7},{%8,%9},{%0,%1,%2,%3};"
        : "+f"(c[0]), "+f"(c[1]), "+f"(c[2]), "+f"(c[3])
        : "r"(a[0]), "r"(a[1]), "r"(a[2]), "r"(a[3]), "r"(b[0]), "r"(b[1]));
}
#define LDS64(r0, r1, addr) \
    asm volatile("ld.shared.v2.u32 {%0,%1}, [%2];" : "=r"(r0), "=r"(r1) : "r"(addr))
#define CP_A16(dst, src) asm volatile("cp.async.ca.shared.global [%0], [%1], 16;" :: "r"(dst), "l"(src))
#define CP_COMMIT()      asm volatile("cp.async.commit_group;" ::: "memory")
#define CP_WAIT2()       asm volatile("cp.async.wait_group 2;" ::: "memory")

// permuted half position within a 16-k group
__device__ __forceinline__ int kperm(int w) {
    return (w & 1) + ((w >> 1) & 3) * 4 + ((w >> 3) & 1) * 2;
}
// fragment LDS.64 byte offset in tile: rows of 32 halves (64B), XOR-16B swizzle.
// g = k16 group (0/1) within stage, lanek in 0..3.
__device__ __forceinline__ uint32_t foff(int row, int g, int lanek) {
    int chunk = (g << 1) + (lanek >> 1);
    return (uint32_t)(row * 64 + ((chunk ^ (row & 3)) << 4) + ((lanek & 1) << 3));
}
__device__ __forceinline__ uint32_t soff(int row, int c) {
    return (uint32_t)(row * 64 + ((c ^ (row & 3)) << 4));
}

// ---------------- convert weights -> permuted fp16 ----------------
__global__ __launch_bounds__(256) void convert_kernel(
    const float* __restrict__ w1, const float* __restrict__ w2,
    const float* __restrict__ w3, const float* __restrict__ sw1,
    const float* __restrict__ sw2, const float* __restrict__ sw3) {
    size_t g = (size_t)blockIdx.x * 256 + threadIdx.x;
    const float* src;
    __half* dst;
    size_t off;
    if      (g < GW)           { src = w1;  dst = g_w1h;  off = g; }
    else if (g < 2 * GW)       { src = w2;  dst = g_w2h;  off = g - GW; }
    else if (g < 3 * GW)       { src = w3;  dst = g_w3h;  off = g - 2 * GW; }
    else if (g < 3 * GW + GS)  { src = sw1; dst = g_sw1h; off = g - 3 * GW; }
    else if (g < 3 * GW + 2 * GS) { src = sw2; dst = g_sw2h; off = g - 3 * GW - GS; }
    else if (g < 3 * GW + 3 * GS) { src = sw3; dst = g_sw3h; off = g - 3 * GW - 2 * GS; }
    else return;
    const float* s = src + off * 16;
    __align__(16) __half tmp[16];
    #pragma unroll
    for (int w = 0; w < 16; w++)
        tmp[kperm(w)] = __float2half_rn(s[w]);
    *(uint4*)(dst + off * 16)     = *(uint4*)tmp;
    *(uint4*)(dst + off * 16 + 8) = *(uint4*)(tmp + 8);
}

// ---------------- routing (+ permuted fp16 x) ----------------
__global__ __launch_bounds__(128) void gate_kernel(const float* __restrict__ x,
                                                   const float* __restrict__ gw) {
    __shared__ float xs[DIMC];
    __shared__ float part[8][E];
    __shared__ float logit[E];
    int t = blockIdx.x;
    for (int i = threadIdx.x; i < DIMC; i += 128) xs[i] = x[(size_t)t * DIMC + i];
    __syncthreads();
    for (int i = threadIdx.x; i < DIMC; i += 128) {
        int pos = (i & ~15) + kperm(i & 15);
        g_xh[(size_t)t * DIMC + pos] = __float2half_rn(xs[i]);
    }
    int e = threadIdx.x & 15, chunk = threadIdx.x >> 4;
    const float* gr = gw + (size_t)e * DIMC + chunk * 128;
    const float* xr = xs + chunk * 128;
    float a0 = 0.f, a1 = 0.f, a2 = 0.f, a3 = 0.f;
    #pragma unroll 8
    for (int i = 0; i < 128; i += 4) {
        a0 += xr[i+0] * gr[i+0]; a1 += xr[i+1] * gr[i+1];
        a2 += xr[i+2] * gr[i+2]; a3 += xr[i+3] * gr[i+3];
    }
    part[chunk][e] = (a0 + a1) + (a2 + a3);
    __syncthreads();
    if (threadIdx.x < E) {
        float s = 0.f;
        #pragma unroll
        for (int c = 0; c < 8; c++) s += part[c][threadIdx.x];
        logit[threadIdx.x] = s;
    }
    __syncthreads();
    if (threadIdx.x == 0) {
        int i0 = 0; float v0 = logit[0];
        #pragma unroll
        for (int i = 1; i < E; i++) if (logit[i] > v0) { v0 = logit[i]; i0 = i; }
        int i1 = -1; float v1 = -1e30f;
        #pragma unroll
        for (int i = 0; i < E; i++) if (i != i0 && logit[i] > v1) { v1 = logit[i]; i1 = i; }
        float s0 = 1.f / (1.f + expf(-v0));
        float s1 = 1.f / (1.f + expf(-v1));
        float inv = 1.f / (s0 + s1);
        g_pair_e[t*2+0] = i0; g_pair_w[t*2+0] = s0 * inv;
        g_pair_e[t*2+1] = i1; g_pair_w[t*2+1] = s1 * inv;
    }
}

__global__ __launch_bounds__(1024) void scatter_kernel() {
    __shared__ int cnt[E], off[E], fill[E];
    if (threadIdx.x < E) { cnt[threadIdx.x] = 0; fill[threadIdx.x] = 0; }
    __syncthreads();
    for (int p = threadIdx.x; p < NP; p += 1024)
        atomicAdd(&cnt[g_pair_e[p]], 1);
    __syncthreads();
    if (threadIdx.x == 0) {
        int s = 0;
        #pragma unroll
        for (int e = 0; e < E; e++) {
            off[e] = s; g_offset[e] = s; g_count[e] = cnt[e]; s += cnt[e];
        }
    }
    __syncthreads();
    for (int p = threadIdx.x; p < NP; p += 1024) {
        int e = g_pair_e[p];
        int slot = off[e] + atomicAdd(&fill[e], 1);
        g_slot_of_pair[p] = slot;
        g_tok_of_slot[slot] = p >> 1;
    }
}

// ---------------------------------------------------------------------------
// SwiGLU GEMM fp16: BM=64, BN=128, dual-B. A = g_xh (gathered).
// ---------------------------------------------------------------------------
__global__ __launch_bounds__(256, 2) void swiglu_gemm() {
    extern __shared__ uint32_t sm[];
    __shared__ int rowsS[64];

    const int z       = blockIdx.z;
    const bool routed = (z < E);
    const int  Ntot   = routed ? INTER : SI;
    if (blockIdx.y * 128 >= Ntot) return;
    const int cnt  = routed ? g_count[z] : T;
    const int m0   = blockIdx.x * 64;
    if (m0 >= cnt) return;
    const int n0   = blockIdx.y * 128;
    const int base = routed ? g_offset[z] : 0;

    const __half* B1 = routed ? (g_w1h + (size_t)z * INTER * DIMC) : g_sw1h;
    const __half* B3 = routed ? (g_w3h + (size_t)z * INTER * DIMC) : g_sw3h;
    __half* C = routed ? g_h : g_hs;

    const int tid    = threadIdx.x;
    const int wid    = tid >> 5;
    const int lane   = tid & 31;
    const int lane4  = lane >> 2;
    const int lanek  = lane & 3;
    const int warp_m = wid & 1;
    const int warp_n = wid >> 1;

    if (tid < 64) {
        int m = m0 + tid;
        rowsS[tid] = routed ? g_tok_of_slot[base + min(m, cnt - 1)]
                            : min(m, cnt - 1);
    }
    __syncthreads();

    const uint32_t smA = smem_u32(sm);
    const uint32_t smB = smA + STAGES * SW_ASTG;
    const uint32_t smC = smB + STAGES * SW_BSTG;

    const int ar = tid >> 2, ac = tid & 3;   // chunk ac covers 8 halves
    const __half* asrc = g_xh + (size_t)rowsS[ar] * DIMC + ac * 8;
    const __half* b1s0 = B1 + (size_t)(n0 + ar) * DIMC + ac * 8;
    const __half* b1s1 = B1 + (size_t)(n0 + 64 + ar) * DIMC + ac * 8;
    const __half* b3s0 = B3 + (size_t)(n0 + ar) * DIMC + ac * 8;
    const __half* b3s1 = B3 + (size_t)(n0 + 64 + ar) * DIMC + ac * 8;
    const uint32_t adst  = smA + soff(ar, ac);
    const uint32_t bdst0 = smB + soff(ar, ac);
    const uint32_t bdst1 = smB + soff(64 + ar, ac);
    const uint32_t cdst0 = smC + soff(ar, ac);
    const uint32_t cdst1 = smC + soff(64 + ar, ac);

    auto issue = [&](int k0, int st) {
        if (k0 < DIMC) {
            CP_A16(adst  + st * SW_ASTG, asrc + k0);
            CP_A16(bdst0 + st * SW_BSTG, b1s0 + k0);
            CP_A16(bdst1 + st * SW_BSTG, b1s1 + k0);
            CP_A16(cdst0 + st * SW_BSTG, b3s0 + k0);
            CP_A16(cdst1 + st * SW_BSTG, b3s1 + k0);
        }
        CP_COMMIT();
    };

    issue(0, 0); issue(BK, 1); issue(2 * BK, 2);

    float acc1[2][4][4] = {};
    float acc3[2][4][4] = {};

    int st = 0;
    for (int k0 = 0; k0 < DIMC; k0 += BK) {
        CP_WAIT2();
        __syncthreads();
        const uint32_t aSt = smA + st * SW_ASTG;
        const uint32_t bSt = smB + st * SW_BSTG;
        const uint32_t cSt = smC + st * SW_BSTG;

        #pragma unroll
        for (int g = 0; g < 2; g++) {
            uint32_t af[2][4];
            #pragma unroll
            for (int fm = 0; fm < 2; fm++) {
                int row = warp_m * 32 + fm * 16 + lane4;
                uint32_t ad = aSt + foff(row, g, lanek);
                LDS64(af[fm][0], af[fm][2], ad);
                LDS64(af[fm][1], af[fm][3], ad + 8 * 64);
            }
            #pragma unroll
            for (int fn = 0; fn < 4; fn++) {
                int rowb = warp_n * 32 + fn * 8 + lane4;
                uint32_t off = foff(rowb, g, lanek);
                uint32_t bf[2], cf[2];
                LDS64(bf[0], bf[1], bSt + off);
                LDS64(cf[0], cf[1], cSt + off);
                mma16(acc1[0][fn], af[0], bf);
                mma16(acc1[1][fn], af[1], bf);
                mma16(acc3[0][fn], af[0], cf);
                mma16(acc3[1][fn], af[1], cf);
            }
        }
        issue(k0 + 3 * BK, (k0 / BK + 3) & (STAGES - 1));
        st = (st + 1) & (STAGES - 1);
    }

    // epilogue: SwiGLU -> permuted fp16 (down reads as pre-permuted A)
    #pragma unroll
    for (int fm = 0; fm < 2; fm++) {
        #pragma unroll
        for (int half = 0; half < 2; half++) {
            int mi = warp_m * 32 + fm * 16 + half * 8 + lane4;
            int m  = m0 + mi;
            if (m >= cnt) continue;
            size_t crow = routed ? (size_t)(base + m) : (size_t)m;
            #pragma unroll
            for (int fn = 0; fn < 4; fn++) {
                int c = n0 + warp_n * 32 + lanek * 2 + fn * 8;   // even
                int w2i = (c & 15) >> 1;
                int q = ((w2i & 3) << 1) + (w2i >> 2);
                int idx = (c & ~15) + (q << 1);
                float v0 = acc1[fm][fn][half * 2 + 0];
                float v1 = acc1[fm][fn][half * 2 + 1];
                float sx = (v0 / (1.f + __expf(-v0))) * acc3[fm][fn][half * 2 + 0];
                float sy = (v1 / (1.f + __expf(-v1))) * acc3[fm][fn][half * 2 + 1];
                *(__half2*)(C + crow * Ntot + idx) = __floats2half2_rn(sx, sy);
            }
        }
    }
}

// ---------------------------------------------------------------------------
// Down GEMM fp16: BM=128, BN=128, warp 64x32.
// ---------------------------------------------------------------------------
__global__ __launch_bounds__(256, 2) void down_gemm(float* __restrict__ out) {
    extern __shared__ uint32_t sm[];
    __shared__ int rowsS[128];

    const int z       = blockIdx.z;
    const bool routed = (z < E);
    const int  KD     = routed ? INTER : SI;
    const int cnt  = routed ? g_count[z] : T;
    const int m0   = blockIdx.x * 128;
    if (m0 >= cnt) return;
    const int n0   = blockIdx.y * 128;
    const int base = routed ? g_offset[z] : 0;

    const __half* A  = routed ? g_h : g_hs;
    const __half* B1 = routed ? (g_w2h + (size_t)z * DIMC * INTER) : g_sw2h;
    float* C = routed ? g_rout : out;

    const int tid    = threadIdx.x;
    const int wid    = tid >> 5;
    const int lane   = tid & 31;
    const int lane4  = lane >> 2;
    const int lanek  = lane & 3;
    const int warp_m = wid & 1;
    const int warp_n = wid >> 1;

    if (tid < 128) {
        int mm = m0 + tid;
        if (mm >= cnt) mm = cnt - 1;
        rowsS[tid] = routed ? (base + mm) : mm;
    }
    __syncthreads();

    const uint32_t smA = smem_u32(sm);
    const uint32_t smB = smA + STAGES * DN_ASTG;

    const int ar0 = tid >> 2, ar1 = 64 + (tid >> 2), ac = tid & 3;
    const __half* asrc0 = A  + (size_t)rowsS[ar0] * KD + ac * 8;
    const __half* asrc1 = A  + (size_t)rowsS[ar1] * KD + ac * 8;
    const __half* bsrc0 = B1 + (size_t)(n0 + ar0) * KD + ac * 8;
    const __half* bsrc1 = B1 + (size_t)(n0 + ar1) * KD + ac * 8;
    const uint32_t adst0 = smA + soff(ar0, ac);
    const uint32_t adst1 = smA + soff(ar1, ac);
    const uint32_t bdst0 = smB + soff(ar0, ac);
    const uint32_t bdst1 = smB + soff(ar1, ac);

    auto issue = [&](int k0, int st) {
        if (k0 < KD) {
            CP_A16(adst0 + st * DN_ASTG, asrc0 + k0);
            CP_A16(adst1 + st * DN_ASTG, asrc1 + k0);
            CP_A16(bdst0 + st * DN_BSTG, bsrc0 + k0);
            CP_A16(bdst1 + st * DN_BSTG, bsrc1 + k0);
        }
        CP_COMMIT();
    };

    issue(0, 0); issue(BK, 1); issue(2 * BK, 2);

    float acc[4][4][4] = {};

    int st = 0;
    for (int k0 = 0; k0 < KD; k0 += BK) {
        CP_WAIT2();
        __syncthreads();
        const uint32_t aSt = smA + st * DN_ASTG;
        const uint32_t bSt = smB + st * DN_BSTG;

        #pragma unroll
        for (int g = 0; g < 2; g++) {
            uint32_t af[4][4];
            #pragma unroll
            for (int fm = 0; fm < 4; fm++) {
                int row = warp_m * 64 + fm * 16 + lane4;
                uint32_t ad = aSt + foff(row, g, lanek);
                LDS64(af[fm][0], af[fm][2], ad);
                LDS64(af[fm][1], af[fm][3], ad + 8 * 64);
            }
            #pragma unroll
            for (int fn = 0; fn < 4; fn++) {
                int rowb = warp_n * 32 + fn * 8 + lane4;
                uint32_t bf[2];
                LDS64(bf[0], bf[1], bSt + foff(rowb, g, lanek));
                #pragma unroll
                for (int fm = 0; fm < 4; fm++) mma16(acc[fm][fn], af[fm], bf);
            }
        }
        issue(k0 + 3 * BK, (k0 / BK + 3) & (STAGES - 1));
        st = (st + 1) & (STAGES - 1);
    }

    #pragma unroll
    for (int fm = 0; fm < 4; fm++) {
        #pragma unroll
        for (int half = 0; half < 2; half++) {
            int mi = warp_m * 64 + fm * 16 + half * 8 + lane4;
            int m  = m0 + mi;
            if (m >= cnt) continue;
            size_t crow = routed ? (size_t)(base + m) : (size_t)m;
            float* cp = C + crow * DIMC + n0 + warp_n * 32 + lanek * 2;
            #pragma unroll
            for (int fn = 0; fn < 4; fn++) {
                float2 o;
                o.x = acc[fm][fn][half * 2 + 0];
                o.y = acc[fm][fn][half * 2 + 1];
                *(float2*)(cp + fn * 8) = o;
            }
        }
    }
}

__global__ __launch_bounds__(256) void combine_kernel(float* __restrict__ out) {
    int t = blockIdx.x;
    float w0 = g_pair_w[t*2+0], w1 = g_pair_w[t*2+1];
    size_t s0 = (size_t)g_slot_of_pair[t*2+0] * DIMC;
    size_t s1 = (size_t)g_slot_of_pair[t*2+1] * DIMC;
    int d = threadIdx.x * 4;
    float4 o  = *(float4*)(out + (size_t)t * DIMC + d);
    float4 r0 = *(const float4*)(g_rout + s0 + d);
    float4 r1 = *(const float4*)(g_rout + s1 + d);
    o.x += w0 * r0.x + w1 * r1.x;
    o.y += w0 * r0.y + w1 * r1.y;
    o.z += w0 * r0.z + w1 * r1.z;
    o.w += w0 * r0.w + w1 * r1.w;
    *(float4*)(out + (size_t)t * DIMC + d) = o;
}

// ---------------------------------------------------------------------------
extern "C" void kernel_launch(void* const* d_in, const int* in_sizes, int n_in,
                              void* d_out, int out_size) {
    const float* x      = (const float*)d_in[0];
    const float* gate_w = (const float*)d_in[1];
    const float* w1     = (const float*)d_in[2];
    const float* w2     = (const float*)d_in[3];
    const float* w3     = (const float*)d_in[4];
    const float* sw1    = (const float*)d_in[5];
    const float* sw2    = (const float*)d_in[6];
    const float* sw3    = (const float*)d_in[7];
    float* out = (float*)d_out;

    cudaFuncSetAttribute(swiglu_gemm, cudaFuncAttributeMaxDynamicSharedMemorySize, SMEM_SW);
    cudaFuncSetAttribute(down_gemm,   cudaFuncAttributeMaxDynamicSharedMemorySize, SMEM_DN);

    size_t ngroups = 3 * GW + 3 * GS;
    convert_kernel<<<(int)((ngroups + 255) / 256), 256>>>(w1, w2, w3, sw1, sw2, sw3);
    gate_kernel<<<T, 128>>>(x, gate_w);
    scatter_kernel<<<1, 1024>>>();

    swiglu_gemm<<<dim3(T / 64, SI / 128, E + 1), 256, SMEM_SW>>>();
    down_gemm<<<dim3(T / 128, DIMC / 128, E + 1), 256, SMEM_DN>>>(out);

    combine_kernel<<<T, 256>>>(out);
}

// round 14
// speedup vs baseline: 1.5718x; 1.0313x over previous
#include <cuda_runtime.h>
#include <cuda_fp16.h>
#include <cstdint>
#include <math.h>

// ---------------------------------------------------------------------------
// MoE via fp16 mma.sync m16n8k16, cp.async 4-stage pipeline, ldmatrix
// fragment loads, conflict-free (row>>1) XOR swizzle, plain k layout.
//   convert: weights -> fp16 (once)
//   gate: routing + fp16 x copy
//   scatter: histogram + offsets + scatter (1 block)
//   swiglu_gemm merged: z<16 routed (gather) -> g_h(fp16) ; z==16 -> g_hs
//   down_gemm merged:   z<16 routed -> g_rout(fp32) ; z==16 shared -> d_out
//   combine
// ---------------------------------------------------------------------------

namespace {
constexpr int T     = 2048;
constexpr int DIMC  = 1024;
constexpr int E     = 16;
constexpr int NP    = T * 2;
constexpr int INTER = 512;
constexpr int SI    = 1024;

constexpr int BK = 32;               // halves per stage (2 k16 groups)
constexpr int STAGES = 4;
constexpr int SW_ASTG = 64 * 64;     // bytes/stage: 64 rows x 64B(32 halves)
constexpr int SW_BSTG = 128 * 64;
constexpr int SMEM_SW = STAGES * (SW_ASTG + 2 * SW_BSTG);   // 81920
constexpr int DN_ASTG = 128 * 64;
constexpr int DN_BSTG = 128 * 64;
constexpr int SMEM_DN = STAGES * (DN_ASTG + DN_BSTG);       // 65536

constexpr size_t NX = (size_t)T * DIMC;
constexpr size_t NW = (size_t)E * INTER * DIMC;
constexpr size_t NS = (size_t)SI * DIMC;
constexpr size_t GW = NW / 16;
constexpr size_t GS = NS / 16;
}

__device__ int   g_count[E];
__device__ int   g_offset[E];
__device__ int   g_pair_e[NP];
__device__ float g_pair_w[NP];
__device__ int   g_slot_of_pair[NP];
__device__ int   g_tok_of_slot[NP];
__device__ __align__(16) __half g_xh[NX];
__device__ __align__(16) __half g_w1h[NW];
__device__ __align__(16) __half g_w2h[NW];
__device__ __align__(16) __half g_w3h[NW];
__device__ __align__(16) __half g_sw1h[NS];
__device__ __align__(16) __half g_sw2h[NS];
__device__ __align__(16) __half g_sw3h[NS];
__device__ __align__(16) __half g_h[(size_t)NP * INTER];
__device__ __align__(16) __half g_hs[(size_t)T * SI];
__device__ __align__(16) float  g_rout[(size_t)NP * DIMC];

// ---------------- helpers ----------------
__device__ __forceinline__ uint32_t smem_u32(const void* p) {
    uint32_t a;
    asm("{ .reg .u64 t; cvta.to.shared.u64 t, %1; cvt.u32.u64 %0, t; }" : "=r"(a) : "l"(p));
    return a;
}
__device__ __forceinline__ void mma16(float* c, const uint32_t* a, const uint32_t* b) {
    asm volatile(
        "mma.sync.aligned.m16n8k16.row.col.f32.f16.f16.f32 "
        "{%0,%1,%2,%3},{%4,%5,%6,%7},{%8,%9},{%0,%1,%2,%3};"
        : "+f"(c[0]), "+f"(c[1]), "+f"(c[2]), "+f"(c[3])
        : "r"(a[0]), "r"(a[1]), "r"(a[2]), "r"(a[3]), "r"(b[0]), "r"(b[1]));
}
#define LDSM4(r0, r1, r2, r3, addr) \
    asm volatile("ldmatrix.sync.aligned.m8n8.x4.shared.b16 {%0,%1,%2,%3}, [%4];" \
        : "=r"(r0), "=r"(r1), "=r"(r2), "=r"(r3) : "r"(addr))
#define CP_A16(dst, src) asm volatile("cp.async.ca.shared.global [%0], [%1], 16;" :: "r"(dst), "l"(src))
#define CP_COMMIT()      asm volatile("cp.async.commit_group;" ::: "memory")
#define CP_WAIT2()       asm volatile("cp.async.wait_group 2;" ::: "memory")

// conflict-free swizzle: 64B rows, 4x16B chunks, key = (row>>1)&3
__device__ __forceinline__ uint32_t soff(int row, int c) {
    return (uint32_t)(row * 64 + ((c ^ ((row >> 1) & 3)) << 4));
}

// ---------------- convert weights -> fp16 ----------------
__global__ __launch_bounds__(256) void convert_kernel(
    const float* __restrict__ w1, const float* __restrict__ w2,
    const float* __restrict__ w3, const float* __restrict__ sw1,
    const float* __restrict__ sw2, const float* __restrict__ sw3) {
    size_t g = (size_t)blockIdx.x * 256 + threadIdx.x;
    const float* src;
    __half* dst;
    size_t off;
    if      (g < GW)              { src = w1;  dst = g_w1h;  off = g; }
    else if (g < 2 * GW)          { src = w2;  dst = g_w2h;  off = g - GW; }
    else if (g < 3 * GW)          { src = w3;  dst = g_w3h;  off = g - 2 * GW; }
    else if (g < 3 * GW + GS)     { src = sw1; dst = g_sw1h; off = g - 3 * GW; }
    else if (g < 3 * GW + 2 * GS) { src = sw2; dst = g_sw2h; off = g - 3 * GW - GS; }
    else if (g < 3 * GW + 3 * GS) { src = sw3; dst = g_sw3h; off = g - 3 * GW - 2 * GS; }
    else return;
    const float* s = src + off * 16;
    __align__(16) __half tmp[16];
    #pragma unroll
    for (int w = 0; w < 16; w++) tmp[w] = __float2half_rn(s[w]);
    *(uint4*)(dst + off * 16)     = *(uint4*)tmp;
    *(uint4*)(dst + off * 16 + 8) = *(uint4*)(tmp + 8);
}

// ---------------- routing (+ fp16 x) ----------------
__global__ __launch_bounds__(128) void gate_kernel(const float* __restrict__ x,
                                                   const float* __restrict__ gw) {
    __shared__ float xs[DIMC];
    __shared__ float part[8][E];
    __shared__ float logit[E];
    int t = blockIdx.x;
    for (int i = threadIdx.x; i < DIMC; i += 128) xs[i] = x[(size_t)t * DIMC + i];
    __syncthreads();
    for (int i = threadIdx.x; i < DIMC; i += 128)
        g_xh[(size_t)t * DIMC + i] = __float2half_rn(xs[i]);

    int e = threadIdx.x & 15, chunk = threadIdx.x >> 4;
    const float* gr = gw + (size_t)e * DIMC + chunk * 128;
    const float* xr = xs + chunk * 128;
    float a0 = 0.f, a1 = 0.f, a2 = 0.f, a3 = 0.f;
    #pragma unroll 8
    for (int i = 0; i < 128; i += 4) {
        a0 += xr[i+0] * gr[i+0]; a1 += xr[i+1] * gr[i+1];
        a2 += xr[i+2] * gr[i+2]; a3 += xr[i+3] * gr[i+3];
    }
    part[chunk][e] = (a0 + a1) + (a2 + a3);
    __syncthreads();
    if (threadIdx.x < E) {
        float s = 0.f;
        #pragma unroll
        for (int c = 0; c < 8; c++) s += part[c][threadIdx.x];
        logit[threadIdx.x] = s;
    }
    __syncthreads();
    if (threadIdx.x == 0) {
        int i0 = 0; float v0 = logit[0];
        #pragma unroll
        for (int i = 1; i < E; i++) if (logit[i] > v0) { v0 = logit[i]; i0 = i; }
        int i1 = -1; float v1 = -1e30f;
        #pragma unroll
        for (int i = 0; i < E; i++) if (i != i0 && logit[i] > v1) { v1 = logit[i]; i1 = i; }
        float s0 = 1.f / (1.f + expf(-v0));
        float s1 = 1.f / (1.f + expf(-v1));
        float inv = 1.f / (s0 + s1);
        g_pair_e[t*2+0] = i0; g_pair_w[t*2+0] = s0 * inv;
        g_pair_e[t*2+1] = i1; g_pair_w[t*2+1] = s1 * inv;
    }
}

__global__ __launch_bounds__(1024) void scatter_kernel() {
    __shared__ int cnt[E], off[E], fill[E];
    if (threadIdx.x < E) { cnt[threadIdx.x] = 0; fill[threadIdx.x] = 0; }
    __syncthreads();
    for (int p = threadIdx.x; p < NP; p += 1024)
        atomicAdd(&cnt[g_pair_e[p]], 1);
    __syncthreads();
    if (threadIdx.x == 0) {
        int s = 0;
        #pragma unroll
        for (int e = 0; e < E; e++) {
            off[e] = s; g_offset[e] = s; g_count[e] = cnt[e]; s += cnt[e];
        }
    }
    __syncthreads();
    for (int p = threadIdx.x; p < NP; p += 1024) {
        int e = g_pair_e[p];
        int slot = off[e] + atomicAdd(&fill[e], 1);
        g_slot_of_pair[p] = slot;
        g_tok_of_slot[slot] = p >> 1;
    }
}

// ---------------------------------------------------------------------------
// SwiGLU GEMM fp16: BM=64, BN=128, dual-B, ldmatrix fragments.
// ---------------------------------------------------------------------------
__global__ __launch_bounds__(256, 2) void swiglu_gemm() {
    extern __shared__ uint32_t sm[];
    __shared__ int rowsS[64];

    const int z       = blockIdx.z;
    const bool routed = (z < E);
    const int  Ntot   = routed ? INTER : SI;
    if (blockIdx.y * 128 >= Ntot) return;
    const int cnt  = routed ? g_count[z] : T;
    const int m0   = blockIdx.x * 64;
    if (m0 >= cnt) return;
    const int n0   = blockIdx.y * 128;
    const int base = routed ? g_offset[z] : 0;

    const __half* B1 = routed ? (g_w1h + (size_t)z * INTER * DIMC) : g_sw1h;
    const __half* B3 = routed ? (g_w3h + (size_t)z * INTER * DIMC) : g_sw3h;
    __half* C = routed ? g_h : g_hs;

    const int tid    = threadIdx.x;
    const int wid    = tid >> 5;
    const int lane   = tid & 31;
    const int lane4  = lane >> 2;
    const int lanek  = lane & 3;
    const int warp_m = wid & 1;
    const int warp_n = wid >> 1;

    if (tid < 64) {
        int m = m0 + tid;
        rowsS[tid] = routed ? g_tok_of_slot[base + min(m, cnt - 1)]
                            : min(m, cnt - 1);
    }
    __syncthreads();

    const uint32_t smA = smem_u32(sm);
    const uint32_t smB = smA + STAGES * SW_ASTG;
    const uint32_t smC = smB + STAGES * SW_BSTG;

    // cp.async fill slots
    const int ar = tid >> 2, ac = tid & 3;
    const __half* asrc = g_xh + (size_t)rowsS[ar] * DIMC + ac * 8;
    const __half* b1s0 = B1 + (size_t)(n0 + ar) * DIMC + ac * 8;
    const __half* b1s1 = B1 + (size_t)(n0 + 64 + ar) * DIMC + ac * 8;
    const __half* b3s0 = B3 + (size_t)(n0 + ar) * DIMC + ac * 8;
    const __half* b3s1 = B3 + (size_t)(n0 + 64 + ar) * DIMC + ac * 8;
    const uint32_t adst  = smA + soff(ar, ac);
    const uint32_t bdst0 = smB + soff(ar, ac);
    const uint32_t bdst1 = smB + soff(64 + ar, ac);
    const uint32_t cdst0 = smC + soff(ar, ac);
    const uint32_t cdst1 = smC + soff(64 + ar, ac);

    auto issue = [&](int k0, int st) {
        if (k0 < DIMC) {
            CP_A16(adst  + st * SW_ASTG, asrc + k0);
            CP_A16(bdst0 + st * SW_BSTG, b1s0 + k0);
            CP_A16(bdst1 + st * SW_BSTG, b1s1 + k0);
            CP_A16(cdst0 + st * SW_BSTG, b3s0 + k0);
            CP_A16(cdst1 + st * SW_BSTG, b3s1 + k0);
        }
        CP_COMMIT();
    };

    issue(0, 0); issue(BK, 1); issue(2 * BK, 2);

    // ldmatrix address precompute
    const int mat  = lane >> 3, mrow = lane & 7;
    const int cbA  = mat >> 1;            // A: k-half select
    const int cbB  = mat & 1;             // B: k-half select
    int arow[2], akey[2], brow[2], bkey[2];
    #pragma unroll
    for (int fm = 0; fm < 2; fm++) {
        int r = warp_m * 32 + fm * 16 + ((mat & 1) << 3) + mrow;
        arow[fm] = r * 64; akey[fm] = (r >> 1) & 3;
    }
    #pragma unroll
    for (int fn2 = 0; fn2 < 2; fn2++) {
        int r = warp_n * 32 + fn2 * 16 + ((mat >> 1) << 3) + mrow;
        brow[fn2] = r * 64; bkey[fn2] = (r >> 1) & 3;
    }

    float acc1[2][4][4] = {};
    float acc3[2][4][4] = {};

    int st = 0;
    for (int k0 = 0; k0 < DIMC; k0 += BK) {
        CP_WAIT2();
        __syncthreads();
        const uint32_t aSt = smA + st * SW_ASTG;
        const uint32_t bSt = smB + st * SW_BSTG;
        const uint32_t cSt = smC + st * SW_BSTG;

        #pragma unroll
        for (int g = 0; g < 2; g++) {
            uint32_t af[2][4];
            #pragma unroll
            for (int fm = 0; fm < 2; fm++) {
                uint32_t ad = aSt + arow[fm] + ((((g << 1) + cbA) ^ akey[fm]) << 4);
                LDSM4(af[fm][0], af[fm][1], af[fm][2], af[fm][3], ad);
            }
            #pragma unroll
            for (int fn2 = 0; fn2 < 2; fn2++) {
                uint32_t boff = brow[fn2] + ((((g << 1) + cbB) ^ bkey[fn2]) << 4);
                uint32_t bf[4], cf[4];
                LDSM4(bf[0], bf[1], bf[2], bf[3], bSt + boff);
                LDSM4(cf[0], cf[1], cf[2], cf[3], cSt + boff);
                mma16(acc1[0][fn2 * 2 + 0], af[0], bf + 0);
                mma16(acc1[0][fn2 * 2 + 1], af[0], bf + 2);
                mma16(acc1[1][fn2 * 2 + 0], af[1], bf + 0);
                mma16(acc1[1][fn2 * 2 + 1], af[1], bf + 2);
                mma16(acc3[0][fn2 * 2 + 0], af[0], cf + 0);
                mma16(acc3[0][fn2 * 2 + 1], af[0], cf + 2);
                mma16(acc3[1][fn2 * 2 + 0], af[1], cf + 0);
                mma16(acc3[1][fn2 * 2 + 1], af[1], cf + 2);
            }
        }
        issue(k0 + 3 * BK, (k0 / BK + 3) & (STAGES - 1));
        st = (st + 1) & (STAGES - 1);
    }

    // epilogue: SwiGLU -> fp16 (plain layout)
    #pragma unroll
    for (int fm = 0; fm < 2; fm++) {
        #pragma unroll
        for (int half = 0; half < 2; half++) {
            int mi = warp_m * 32 + fm * 16 + half * 8 + lane4;
            int m  = m0 + mi;
            if (m >= cnt) continue;
            size_t crow = routed ? (size_t)(base + m) : (size_t)m;
            #pragma unroll
            for (int fn = 0; fn < 4; fn++) {
                int c = n0 + warp_n * 32 + fn * 8 + lanek * 2;
                float v0 = acc1[fm][fn][half * 2 + 0];
                float v1 = acc1[fm][fn][half * 2 + 1];
                float sx = (v0 / (1.f + __expf(-v0))) * acc3[fm][fn][half * 2 + 0];
                float sy = (v1 / (1.f + __expf(-v1))) * acc3[fm][fn][half * 2 + 1];
                *(__half2*)(C + crow * Ntot + c) = __floats2half2_rn(sx, sy);
            }
        }
    }
}

// ---------------------------------------------------------------------------
// Down GEMM fp16: BM=128, BN=128, warp 64x32, ldmatrix fragments.
// ---------------------------------------------------------------------------
__global__ __launch_bounds__(256, 2) void down_gemm(float* __restrict__ out) {
    extern __shared__ uint32_t sm[];
    __shared__ int rowsS[128];

    const int z       = blockIdx.z;
    const bool routed = (z < E);
    const int  KD     = routed ? INTER : SI;
    const int cnt  = routed ? g_count[z] : T;
    const int m0   = blockIdx.x * 128;
    if (m0 >= cnt) return;
    const int n0   = blockIdx.y * 128;
    const int base = routed ? g_offset[z] : 0;

    const __half* A  = routed ? g_h : g_hs;
    const __half* B1 = routed ? (g_w2h + (size_t)z * DIMC * INTER) : g_sw2h;
    float* C = routed ? g_rout : out;

    const int tid    = threadIdx.x;
    const int wid    = tid >> 5;
    const int lane   = tid & 31;
    const int lane4  = lane >> 2;
    const int lanek  = lane & 3;
    const int warp_m = wid & 1;
    const int warp_n = wid >> 1;

    if (tid < 128) {
        int mm = m0 + tid;
        if (mm >= cnt) mm = cnt - 1;
        rowsS[tid] = routed ? (base + mm) : mm;
    }
    __syncthreads();

    const uint32_t smA = smem_u32(sm);
    const uint32_t smB = smA + STAGES * DN_ASTG;

    const int ar0 = tid >> 2, ar1 = 64 + (tid >> 2), ac = tid & 3;
    const __half* asrc0 = A  + (size_t)rowsS[ar0] * KD + ac * 8;
    const __half* asrc1 = A  + (size_t)rowsS[ar1] * KD + ac * 8;
    const __half* bsrc0 = B1 + (size_t)(n0 + ar0) * KD + ac * 8;
    const __half* bsrc1 = B1 + (size_t)(n0 + ar1) * KD + ac * 8;
    const uint32_t adst0 = smA + soff(ar0, ac);
    const uint32_t adst1 = smA + soff(ar1, ac);
    const uint32_t bdst0 = smB + soff(ar0, ac);
    const uint32_t bdst1 = smB + soff(ar1, ac);

    auto issue = [&](int k0, int st) {
        if (k0 < KD) {
            CP_A16(adst0 + st * DN_ASTG, asrc0 + k0);
            CP_A16(adst1 + st * DN_ASTG, asrc1 + k0);
            CP_A16(bdst0 + st * DN_BSTG, bsrc0 + k0);
            CP_A16(bdst1 + st * DN_BSTG, bsrc1 + k0);
        }
        CP_COMMIT();
    };

    issue(0, 0); issue(BK, 1); issue(2 * BK, 2);

    const int mat  = lane >> 3, mrow = lane & 7;
    const int cbA  = mat >> 1;
    const int cbB  = mat & 1;
    int arow[4], akey[4], brow[2], bkey[2];
    #pragma unroll
    for (int fm = 0; fm < 4; fm++) {
        int r = warp_m * 64 + fm * 16 + ((mat & 1) << 3) + mrow;
        arow[fm] = r * 64; akey[fm] = (r >> 1) & 3;
    }
    #pragma unroll
    for (int fn2 = 0; fn2 < 2; fn2++) {
        int r = warp_n * 32 + fn2 * 16 + ((mat >> 1) << 3) + mrow;
        brow[fn2] = r * 64; bkey[fn2] = (r >> 1) & 3;
    }

    float acc[4][4][4] = {};

    int st = 0;
    for (int k0 = 0; k0 < KD; k0 += BK) {
        CP_WAIT2();
        __syncthreads();
        const uint32_t aSt = smA + st * DN_ASTG;
        const uint32_t bSt = smB + st * DN_BSTG;

        #pragma unroll
        for (int g = 0; g < 2; g++) {
            uint32_t af[4][4];
            #pragma unroll
            for (int fm = 0; fm < 4; fm++) {
                uint32_t ad = aSt + arow[fm] + ((((g << 1) + cbA) ^ akey[fm]) << 4);
                LDSM4(af[fm][0], af[fm][1], af[fm][2], af[fm][3], ad);
            }
            #pragma unroll
            for (int fn2 = 0; fn2 < 2; fn2++) {
                uint32_t bf[4];
                uint32_t boff = brow[fn2] + ((((g << 1) + cbB) ^ bkey[fn2]) << 4);
                LDSM4(bf[0], bf[1], bf[2], bf[3], bSt + boff);
                #pragma unroll
                for (int fm = 0; fm < 4; fm++) {
                    mma16(acc[fm][fn2 * 2 + 0], af[fm], bf + 0);
                    mma16(acc[fm][fn2 * 2 + 1], af[fm], bf + 2);
                }
            }
        }
        issue(k0 + 3 * BK, (k0 / BK + 3) & (STAGES - 1));
        st = (st + 1) & (STAGES - 1);
    }

    #pragma unroll
    for (int fm = 0; fm < 4; fm++) {
        #pragma unroll
        for (int half = 0; half < 2; half++) {
            int mi = warp_m * 64 + fm * 16 + half * 8 + lane4;
            int m  = m0 + mi;
            if (m >= cnt) continue;
            size_t crow = routed ? (size_t)(base + m) : (size_t)m;
            float* cp = C + crow * DIMC + n0 + warp_n * 32 + lanek * 2;
            #pragma unroll
            for (int fn = 0; fn < 4; fn++) {
                float2 o;
                o.x = acc[fm][fn][half * 2 + 0];
                o.y = acc[fm][fn][half * 2 + 1];
                *(float2*)(cp + fn * 8) = o;
            }
        }
    }
}

__global__ __launch_bounds__(256) void combine_kernel(float* __restrict__ out) {
    int t = blockIdx.x;
    float w0 = g_pair_w[t*2+0], w1 = g_pair_w[t*2+1];
    size_t s0 = (size_t)g_slot_of_pair[t*2+0] * DIMC;
    size_t s1 = (size_t)g_slot_of_pair[t*2+1] * DIMC;
    int d = threadIdx.x * 4;
    float4 o  = *(float4*)(out + (size_t)t * DIMC + d);
    float4 r0 = *(const float4*)(g_rout + s0 + d);
    float4 r1 = *(const float4*)(g_rout + s1 + d);
    o.x += w0 * r0.x + w1 * r1.x;
    o.y += w0 * r0.y + w1 * r1.y;
    o.z += w0 * r0.z + w1 * r1.z;
    o.w += w0 * r0.w + w1 * r1.w;
    *(float4*)(out + (size_t)t * DIMC + d) = o;
}

// ---------------------------------------------------------------------------
extern "C" void kernel_launch(void* const* d_in, const int* in_sizes, int n_in,
                              void* d_out, int out_size) {
    const float* x      = (const float*)d_in[0];
    const float* gate_w = (const float*)d_in[1];
    const float* w1     = (const float*)d_in[2];
    const float* w2     = (const float*)d_in[3];
    const float* w3     = (const float*)d_in[4];
    const float* sw1    = (const float*)d_in[5];
    const float* sw2    = (const float*)d_in[6];
    const float* sw3    = (const float*)d_in[7];
    float* out = (float*)d_out;

    cudaFuncSetAttribute(swiglu_gemm, cudaFuncAttributeMaxDynamicSharedMemorySize, SMEM_SW);
    cudaFuncSetAttribute(down_gemm,   cudaFuncAttributeMaxDynamicSharedMemorySize, SMEM_DN);

    size_t ngroups = 3 * GW + 3 * GS;
    convert_kernel<<<(int)((ngroups + 255) / 256), 256>>>(w1, w2, w3, sw1, sw2, sw3);
    gate_kernel<<<T, 128>>>(x, gate_w);
    scatter_kernel<<<1, 1024>>>();

    swiglu_gemm<<<dim3(T / 64, SI / 128, E + 1), 256, SMEM_SW>>>();
    down_gemm<<<dim3(T / 128, DIMC / 128, E + 1), 256, SMEM_DN>>>(out);

    combine_kernel<<<T, 256>>>(out);
}

// round 15
// speedup vs baseline: 1.9023x; 1.2103x over previous
#include <cuda_runtime.h>
#include <cuda_fp16.h>
#include <cstdint>
#include <math.h>

// ---------------------------------------------------------------------------
// MoE via fp16 mma.sync m16n8k16, cp.async(cg) 4-stage pipeline, ldmatrix,
// conflict-free (row>>1) XOR swizzle. Two-stream graph-captured overlap:
//   main:  gate -> scatter -> [wait conv] swiglu_r -> down_r -> [wait sh] combine
//   s2:    convert -> [wait gate] swiglu_sh -> down_sh(out)
// ---------------------------------------------------------------------------

namespace {
constexpr int T     = 2048;
constexpr int DIMC  = 1024;
constexpr int E     = 16;
constexpr int NP    = T * 2;
constexpr int INTER = 512;
constexpr int SI    = 1024;

constexpr int BK = 32;               // halves per stage (2 k16 groups)
constexpr int STAGES = 4;
constexpr int SW_ASTG = 64 * 64;
constexpr int SW_BSTG = 128 * 64;
constexpr int SMEM_SW = STAGES * (SW_ASTG + 2 * SW_BSTG);   // 81920
constexpr int DN_ASTG = 128 * 64;
constexpr int DN_BSTG = 128 * 64;
constexpr int SMEM_DN = STAGES * (DN_ASTG + DN_BSTG);       // 65536

constexpr size_t NX = (size_t)T * DIMC;
constexpr size_t NW = (size_t)E * INTER * DIMC;
constexpr size_t NS = (size_t)SI * DIMC;
constexpr size_t GW = NW / 16;
constexpr size_t GS = NS / 16;
}

__device__ int   g_count[E];
__device__ int   g_offset[E];
__device__ int   g_pair_e[NP];
__device__ float g_pair_w[NP];
__device__ int   g_slot_of_pair[NP];
__device__ int   g_tok_of_slot[NP];
__device__ __align__(16) __half g_xh[NX];
__device__ __align__(16) __half g_w1h[NW];
__device__ __align__(16) __half g_w2h[NW];
__device__ __align__(16) __half g_w3h[NW];
__device__ __align__(16) __half g_sw1h[NS];
__device__ __align__(16) __half g_sw2h[NS];
__device__ __align__(16) __half g_sw3h[NS];
__device__ __align__(16) __half g_h[(size_t)NP * INTER];
__device__ __align__(16) __half g_hs[(size_t)T * SI];
__device__ __align__(16) float  g_rout[(size_t)NP * DIMC];

// ---------------- helpers ----------------
__device__ __forceinline__ uint32_t smem_u32(const void* p) {
    uint32_t a;
    asm("{ .reg .u64 t; cvta.to.shared.u64 t, %1; cvt.u32.u64 %0, t; }" : "=r"(a) : "l"(p));
    return a;
}
__device__ __forceinline__ void mma16(float* c, const uint32_t* a, const uint32_t* b) {
    asm volatile(
        "mma.sync.aligned.m16n8k16.row.col.f32.f16.f16.f32 "
        "{%0,%1,%2,%3},{%4,%5,%6,%7},{%8,%9},{%0,%1,%2,%3};"
        : "+f"(c[0]), "+f"(c[1]), "+f"(c[2]), "+f"(c[3])
        : "r"(a[0]), "r"(a[1]), "r"(a[2]), "r"(a[3]), "r"(b[0]), "r"(b[1]));
}
#define LDSM4(r0, r1, r2, r3, addr) \
    asm volatile("ldmatrix.sync.aligned.m8n8.x4.shared.b16 {%0,%1,%2,%3}, [%4];" \
        : "=r"(r0), "=r"(r1), "=r"(r2), "=r"(r3) : "r"(addr))
#define CP_A16(dst, src) asm volatile("cp.async.cg.shared.global [%0], [%1], 16;" :: "r"(dst), "l"(src))
#define CP_COMMIT()      asm volatile("cp.async.commit_group;" ::: "memory")
#define CP_WAIT2()       asm volatile("cp.async.wait_group 2;" ::: "memory")

// conflict-free swizzle: 64B rows, 4x16B chunks, key = (row>>1)&3
__device__ __forceinline__ uint32_t soff(int row, int c) {
    return (uint32_t)(row * 64 + ((c ^ ((row >> 1) & 3)) << 4));
}

// ---------------- convert weights -> fp16 ----------------
__global__ __launch_bounds__(256) void convert_kernel(
    const float* __restrict__ w1, const float* __restrict__ w2,
    const float* __restrict__ w3, const float* __restrict__ sw1,
    const float* __restrict__ sw2, const float* __restrict__ sw3) {
    size_t g = (size_t)blockIdx.x * 256 + threadIdx.x;
    const float* src;
    __half* dst;
    size_t off;
    if      (g < GW)              { src = w1;  dst = g_w1h;  off = g; }
    else if (g < 2 * GW)          { src = w2;  dst = g_w2h;  off = g - GW; }
    else if (g < 3 * GW)          { src = w3;  dst = g_w3h;  off = g - 2 * GW; }
    else if (g < 3 * GW + GS)     { src = sw1; dst = g_sw1h; off = g - 3 * GW; }
    else if (g < 3 * GW + 2 * GS) { src = sw2; dst = g_sw2h; off = g - 3 * GW - GS; }
    else if (g < 3 * GW + 3 * GS) { src = sw3; dst = g_sw3h; off = g - 3 * GW - 2 * GS; }
    else return;
    const float4* s4 = (const float4*)(src + off * 16);
    float4 v0 = s4[0], v1 = s4[1], v2 = s4[2], v3 = s4[3];
    __align__(16) __half tmp[16];
    tmp[0]=__float2half_rn(v0.x); tmp[1]=__float2half_rn(v0.y);
    tmp[2]=__float2half_rn(v0.z); tmp[3]=__float2half_rn(v0.w);
    tmp[4]=__float2half_rn(v1.x); tmp[5]=__float2half_rn(v1.y);
    tmp[6]=__float2half_rn(v1.z); tmp[7]=__float2half_rn(v1.w);
    tmp[8]=__float2half_rn(v2.x); tmp[9]=__float2half_rn(v2.y);
    tmp[10]=__float2half_rn(v2.z); tmp[11]=__float2half_rn(v2.w);
    tmp[12]=__float2half_rn(v3.x); tmp[13]=__float2half_rn(v3.y);
    tmp[14]=__float2half_rn(v3.z); tmp[15]=__float2half_rn(v3.w);
    *(uint4*)(dst + off * 16)     = *(uint4*)tmp;
    *(uint4*)(dst + off * 16 + 8) = *(uint4*)(tmp + 8);
}

// ---------------- routing (+ fp16 x) ----------------
__global__ __launch_bounds__(128) void gate_kernel(const float* __restrict__ x,
                                                   const float* __restrict__ gw) {
    __shared__ float xs[DIMC];
    __shared__ float part[8][E];
    __shared__ float logit[E];
    int t = blockIdx.x;
    for (int i = threadIdx.x; i < DIMC; i += 128) xs[i] = x[(size_t)t * DIMC + i];
    __syncthreads();
    for (int i = threadIdx.x; i < DIMC; i += 128)
        g_xh[(size_t)t * DIMC + i] = __float2half_rn(xs[i]);

    int e = threadIdx.x & 15, chunk = threadIdx.x >> 4;
    const float* gr = gw + (size_t)e * DIMC + chunk * 128;
    const float* xr = xs + chunk * 128;
    float a0 = 0.f, a1 = 0.f, a2 = 0.f, a3 = 0.f;
    #pragma unroll 8
    for (int i = 0; i < 128; i += 4) {
        a0 += xr[i+0] * gr[i+0]; a1 += xr[i+1] * gr[i+1];
        a2 += xr[i+2] * gr[i+2]; a3 += xr[i+3] * gr[i+3];
    }
    part[chunk][e] = (a0 + a1) + (a2 + a3);
    __syncthreads();
    if (threadIdx.x < E) {
        float s = 0.f;
        #pragma unroll
        for (int c = 0; c < 8; c++) s += part[c][threadIdx.x];
        logit[threadIdx.x] = s;
    }
    __syncthreads();
    if (threadIdx.x == 0) {
        int i0 = 0; float v0 = logit[0];
        #pragma unroll
        for (int i = 1; i < E; i++) if (logit[i] > v0) { v0 = logit[i]; i0 = i; }
        int i1 = -1; float v1 = -1e30f;
        #pragma unroll
        for (int i = 0; i < E; i++) if (i != i0 && logit[i] > v1) { v1 = logit[i]; i1 = i; }
        float s0 = 1.f / (1.f + expf(-v0));
        float s1 = 1.f / (1.f + expf(-v1));
        float inv = 1.f / (s0 + s1);
        g_pair_e[t*2+0] = i0; g_pair_w[t*2+0] = s0 * inv;
        g_pair_e[t*2+1] = i1; g_pair_w[t*2+1] = s1 * inv;
    }
}

__global__ __launch_bounds__(1024) void scatter_kernel() {
    __shared__ int cnt[E], off[E], fill[E];
    if (threadIdx.x < E) { cnt[threadIdx.x] = 0; fill[threadIdx.x] = 0; }
    __syncthreads();
    for (int p = threadIdx.x; p < NP; p += 1024)
        atomicAdd(&cnt[g_pair_e[p]], 1);
    __syncthreads();
    if (threadIdx.x == 0) {
        int s = 0;
        #pragma unroll
        for (int e = 0; e < E; e++) {
            off[e] = s; g_offset[e] = s; g_count[e] = cnt[e]; s += cnt[e];
        }
    }
    __syncthreads();
    for (int p = threadIdx.x; p < NP; p += 1024) {
        int e = g_pair_e[p];
        int slot = off[e] + atomicAdd(&fill[e], 1);
        g_slot_of_pair[p] = slot;
        g_tok_of_slot[slot] = p >> 1;
    }
}

// ---------------------------------------------------------------------------
// SwiGLU GEMM fp16: BM=64, BN=128, dual-B, ldmatrix. shared_mode arg.
// ---------------------------------------------------------------------------
__global__ __launch_bounds__(256, 2) void swiglu_gemm(int shared_mode) {
    extern __shared__ uint32_t sm[];
    __shared__ int rowsS[64];

    const bool routed = !shared_mode;
    const int  z      = routed ? blockIdx.z : 0;
    const int  Ntot   = routed ? INTER : SI;
    const int cnt  = routed ? g_count[z] : T;
    const int m0   = blockIdx.x * 64;
    if (m0 >= cnt) return;
    const int n0   = blockIdx.y * 128;
    const int base = routed ? g_offset[z] : 0;

    const __half* B1 = routed ? (g_w1h + (size_t)z * INTER * DIMC) : g_sw1h;
    const __half* B3 = routed ? (g_w3h + (size_t)z * INTER * DIMC) : g_sw3h;
    __half* C = routed ? g_h : g_hs;

    const int tid    = threadIdx.x;
    const int wid    = tid >> 5;
    const int lane   = tid & 31;
    const int lane4  = lane >> 2;
    const int lanek  = lane & 3;
    const int warp_m = wid & 1;
    const int warp_n = wid >> 1;

    if (tid < 64) {
        int m = m0 + tid;
        rowsS[tid] = routed ? g_tok_of_slot[base + min(m, cnt - 1)]
                            : min(m, cnt - 1);
    }
    __syncthreads();

    const uint32_t smA = smem_u32(sm);
    const uint32_t smB = smA + STAGES * SW_ASTG;
    const uint32_t smC = smB + STAGES * SW_BSTG;

    const int ar = tid >> 2, ac = tid & 3;
    const __half* asrc = g_xh + (size_t)rowsS[ar] * DIMC + ac * 8;
    const __half* b1s0 = B1 + (size_t)(n0 + ar) * DIMC + ac * 8;
    const __half* b1s1 = B1 + (size_t)(n0 + 64 + ar) * DIMC + ac * 8;
    const __half* b3s0 = B3 + (size_t)(n0 + ar) * DIMC + ac * 8;
    const __half* b3s1 = B3 + (size_t)(n0 + 64 + ar) * DIMC + ac * 8;
    const uint32_t adst  = smA + soff(ar, ac);
    const uint32_t bdst0 = smB + soff(ar, ac);
    const uint32_t bdst1 = smB + soff(64 + ar, ac);
    const uint32_t cdst0 = smC + soff(ar, ac);
    const uint32_t cdst1 = smC + soff(64 + ar, ac);

    auto issue = [&](int k0, int st) {
        if (k0 < DIMC) {
            CP_A16(adst  + st * SW_ASTG, asrc + k0);
            CP_A16(bdst0 + st * SW_BSTG, b1s0 + k0);
            CP_A16(bdst1 + st * SW_BSTG, b1s1 + k0);
            CP_A16(cdst0 + st * SW_BSTG, b3s0 + k0);
            CP_A16(cdst1 + st * SW_BSTG, b3s1 + k0);
        }
        CP_COMMIT();
    };

    issue(0, 0); issue(BK, 1); issue(2 * BK, 2);

    const int mat  = lane >> 3, mrow = lane & 7;
    const int cbA  = mat >> 1;
    const int cbB  = mat & 1;
    int arow[2], akey[2], brow[2], bkey[2];
    #pragma unroll
    for (int fm = 0; fm < 2; fm++) {
        int r = warp_m * 32 + fm * 16 + ((mat & 1) << 3) + mrow;
        arow[fm] = r * 64; akey[fm] = (r >> 1) & 3;
    }
    #pragma unroll
    for (int fn2 = 0; fn2 < 2; fn2++) {
        int r = warp_n * 32 + fn2 * 16 + ((mat >> 1) << 3) + mrow;
        brow[fn2] = r * 64; bkey[fn2] = (r >> 1) & 3;
    }

    float acc1[2][4][4] = {};
    float acc3[2][4][4] = {};

    int st = 0;
    for (int k0 = 0; k0 < DIMC; k0 += BK) {
        CP_WAIT2();
        __syncthreads();
        const uint32_t aSt = smA + st * SW_ASTG;
        const uint32_t bSt = smB + st * SW_BSTG;
        const uint32_t cSt = smC + st * SW_BSTG;

        #pragma unroll
        for (int g = 0; g < 2; g++) {
            uint32_t af[2][4];
            #pragma unroll
            for (int fm = 0; fm < 2; fm++) {
                uint32_t ad = aSt + arow[fm] + ((((g << 1) + cbA) ^ akey[fm]) << 4);
                LDSM4(af[fm][0], af[fm][1], af[fm][2], af[fm][3], ad);
            }
            #pragma unroll
            for (int fn2 = 0; fn2 < 2; fn2++) {
                uint32_t boff = brow[fn2] + ((((g << 1) + cbB) ^ bkey[fn2]) << 4);
                uint32_t bf[4], cf[4];
                LDSM4(bf[0], bf[1], bf[2], bf[3], bSt + boff);
                LDSM4(cf[0], cf[1], cf[2], cf[3], cSt + boff);
                mma16(acc1[0][fn2 * 2 + 0], af[0], bf + 0);
                mma16(acc1[0][fn2 * 2 + 1], af[0], bf + 2);
                mma16(acc1[1][fn2 * 2 + 0], af[1], bf + 0);
                mma16(acc1[1][fn2 * 2 + 1], af[1], bf + 2);
                mma16(acc3[0][fn2 * 2 + 0], af[0], cf + 0);
                mma16(acc3[0][fn2 * 2 + 1], af[0], cf + 2);
                mma16(acc3[1][fn2 * 2 + 0], af[1], cf + 0);
                mma16(acc3[1][fn2 * 2 + 1], af[1], cf + 2);
            }
        }
        issue(k0 + 3 * BK, (k0 / BK + 3) & (STAGES - 1));
        st = (st + 1) & (STAGES - 1);
    }

    #pragma unroll
    for (int fm = 0; fm < 2; fm++) {
        #pragma unroll
        for (int half = 0; half < 2; half++) {
            int mi = warp_m * 32 + fm * 16 + half * 8 + lane4;
            int m  = m0 + mi;
            if (m >= cnt) continue;
            size_t crow = routed ? (size_t)(base + m) : (size_t)m;
            #pragma unroll
            for (int fn = 0; fn < 4; fn++) {
                int c = n0 + warp_n * 32 + fn * 8 + lanek * 2;
                float v0 = acc1[fm][fn][half * 2 + 0];
                float v1 = acc1[fm][fn][half * 2 + 1];
                float sx = (v0 / (1.f + __expf(-v0))) * acc3[fm][fn][half * 2 + 0];
                float sy = (v1 / (1.f + __expf(-v1))) * acc3[fm][fn][half * 2 + 1];
                *(__half2*)(C + crow * Ntot + c) = __floats2half2_rn(sx, sy);
            }
        }
    }
}

// ---------------------------------------------------------------------------
// Down GEMM fp16: BM=128, BN=128, warp 64x32, ldmatrix. shared_mode arg.
// ---------------------------------------------------------------------------
__global__ __launch_bounds__(256, 2) void down_gemm(int shared_mode,
                                                    float* __restrict__ out) {
    extern __shared__ uint32_t sm[];
    __shared__ int rowsS[128];

    const bool routed = !shared_mode;
    const int  z      = routed ? blockIdx.z : 0;
    const int  KD     = routed ? INTER : SI;
    const int cnt  = routed ? g_count[z] : T;
    const int m0   = blockIdx.x * 128;
    if (m0 >= cnt) return;
    const int n0   = blockIdx.y * 128;
    const int base = routed ? g_offset[z] : 0;

    const __half* A  = routed ? g_h : g_hs;
    const __half* B1 = routed ? (g_w2h + (size_t)z * DIMC * INTER) : g_sw2h;
    float* C = routed ? g_rout : out;

    const int tid    = threadIdx.x;
    const int wid    = tid >> 5;
    const int lane   = tid & 31;
    const int lane4  = lane >> 2;
    const int lanek  = lane & 3;
    const int warp_m = wid & 1;
    const int warp_n = wid >> 1;

    if (tid < 128) {
        int mm = m0 + tid;
        if (mm >= cnt) mm = cnt - 1;
        rowsS[tid] = routed ? (base + mm) : mm;
    }
    __syncthreads();

    const uint32_t smA = smem_u32(sm);
    const uint32_t smB = smA + STAGES * DN_ASTG;

    const int ar0 = tid >> 2, ar1 = 64 + (tid >> 2), ac = tid & 3;
    const __half* asrc0 = A  + (size_t)rowsS[ar0] * KD + ac * 8;
    const __half* asrc1 = A  + (size_t)rowsS[ar1] * KD + ac * 8;
    const __half* bsrc0 = B1 + (size_t)(n0 + ar0) * KD + ac * 8;
    const __half* bsrc1 = B1 + (size_t)(n0 + ar1) * KD + ac * 8;
    const uint32_t adst0 = smA + soff(ar0, ac);
    const uint32_t adst1 = smA + soff(ar1, ac);
    const uint32_t bdst0 = smB + soff(ar0, ac);
    const uint32_t bdst1 = smB + soff(ar1, ac);

    auto issue = [&](int k0, int st) {
        if (k0 < KD) {
            CP_A16(adst0 + st * DN_ASTG, asrc0 + k0);
            CP_A16(adst1 + st * DN_ASTG, asrc1 + k0);
            CP_A16(bdst0 + st * DN_BSTG, bsrc0 + k0);
            CP_A16(bdst1 + st * DN_BSTG, bsrc1 + k0);
        }
        CP_COMMIT();
    };

    issue(0, 0); issue(BK, 1); issue(2 * BK, 2);

    const int mat  = lane >> 3, mrow = lane & 7;
    const int cbA  = mat >> 1;
    const int cbB  = mat & 1;
    int arow[4], akey[4], brow[2], bkey[2];
    #pragma unroll
    for (int fm = 0; fm < 4; fm++) {
        int r = warp_m * 64 + fm * 16 + ((mat & 1) << 3) + mrow;
        arow[fm] = r * 64; akey[fm] = (r >> 1) & 3;
    }
    #pragma unroll
    for (int fn2 = 0; fn2 < 2; fn2++) {
        int r = warp_n * 32 + fn2 * 16 + ((mat >> 1) << 3) + mrow;
        brow[fn2] = r * 64; bkey[fn2] = (r >> 1) & 3;
    }

    float acc[4][4][4] = {};

    int st = 0;
    for (int k0 = 0; k0 < KD; k0 += BK) {
        CP_WAIT2();
        __syncthreads();
        const uint32_t aSt = smA + st * DN_ASTG;
        const uint32_t bSt = smB + st * DN_BSTG;

        #pragma unroll
        for (int g = 0; g < 2; g++) {
            uint32_t af[4][4];
            #pragma unroll
            for (int fm = 0; fm < 4; fm++) {
                uint32_t ad = aSt + arow[fm] + ((((g << 1) + cbA) ^ akey[fm]) << 4);
                LDSM4(af[fm][0], af[fm][1], af[fm][2], af[fm][3], ad);
            }
            #pragma unroll
            for (int fn2 = 0; fn2 < 2; fn2++) {
                uint32_t bf[4];
                uint32_t boff = brow[fn2] + ((((g << 1) + cbB) ^ bkey[fn2]) << 4);
                LDSM4(bf[0], bf[1], bf[2], bf[3], bSt + boff);
                #pragma unroll
                for (int fm = 0; fm < 4; fm++) {
                    mma16(acc[fm][fn2 * 2 + 0], af[fm], bf + 0);
                    mma16(acc[fm][fn2 * 2 + 1], af[fm], bf + 2);
                }
            }
        }
        issue(k0 + 3 * BK, (k0 / BK + 3) & (STAGES - 1));
        st = (st + 1) & (STAGES - 1);
    }

    #pragma unroll
    for (int fm = 0; fm < 4; fm++) {
        #pragma unroll
        for (int half = 0; half < 2; half++) {
            int mi = warp_m * 64 + fm * 16 + half * 8 + lane4;
            int m  = m0 + mi;
            if (m >= cnt) continue;
            size_t crow = routed ? (size_t)(base + m) : (size_t)m;
            float* cp = C + crow * DIMC + n0 + warp_n * 32 + lanek * 2;
            #pragma unroll
            for (int fn = 0; fn < 4; fn++) {
                float2 o;
                o.x = acc[fm][fn][half * 2 + 0];
                o.y = acc[fm][fn][half * 2 + 1];
                *(float2*)(cp + fn * 8) = o;
            }
        }
    }
}

__global__ __launch_bounds__(256) void combine_kernel(float* __restrict__ out) {
    int t = blockIdx.x;
    float w0 = g_pair_w[t*2+0], w1 = g_pair_w[t*2+1];
    size_t s0 = (size_t)g_slot_of_pair[t*2+0] * DIMC;
    size_t s1 = (size_t)g_slot_of_pair[t*2+1] * DIMC;
    int d = threadIdx.x * 4;
    float4 o  = *(float4*)(out + (size_t)t * DIMC + d);
    float4 r0 = *(const float4*)(g_rout + s0 + d);
    float4 r1 = *(const float4*)(g_rout + s1 + d);
    o.x += w0 * r0.x + w1 * r1.x;
    o.y += w0 * r0.y + w1 * r1.y;
    o.z += w0 * r0.z + w1 * r1.z;
    o.w += w0 * r0.w + w1 * r1.w;
    *(float4*)(out + (size_t)t * DIMC + d) = o;
}

// ---------------------------------------------------------------------------
extern "C" void kernel_launch(void* const* d_in, const int* in_sizes, int n_in,
                              void* d_out, int out_size) {
    const float* x      = (const float*)d_in[0];
    const float* gate_w = (const float*)d_in[1];
    const float* w1     = (const float*)d_in[2];
    const float* w2     = (const float*)d_in[3];
    const float* w3     = (const float*)d_in[4];
    const float* sw1    = (const float*)d_in[5];
    const float* sw2    = (const float*)d_in[6];
    const float* sw3    = (const float*)d_in[7];
    float* out = (float*)d_out;

    static cudaStream_t s2 = nullptr;
    static cudaEvent_t evFork, evConv, evGate, evShared;
    if (s2 == nullptr) {
        cudaStreamCreateWithFlags(&s2, cudaStreamNonBlocking);
        cudaEventCreateWithFlags(&evFork,   cudaEventDisableTiming);
        cudaEventCreateWithFlags(&evConv,   cudaEventDisableTiming);
        cudaEventCreateWithFlags(&evGate,   cudaEventDisableTiming);
        cudaEventCreateWithFlags(&evShared, cudaEventDisableTiming);
        cudaFuncSetAttribute(swiglu_gemm, cudaFuncAttributeMaxDynamicSharedMemorySize, SMEM_SW);
        cudaFuncSetAttribute(down_gemm,   cudaFuncAttributeMaxDynamicSharedMemorySize, SMEM_DN);
    }

    // fork: convert on s2, routing on main
    cudaEventRecord(evFork, 0);
    cudaStreamWaitEvent(s2, evFork, 0);

    size_t ngroups = 3 * GW + 3 * GS;
    convert_kernel<<<(int)((ngroups + 255) / 256), 256, 0, s2>>>(w1, w2, w3, sw1, sw2, sw3);
    cudaEventRecord(evConv, s2);

    gate_kernel<<<T, 128>>>(x, gate_w);
    cudaEventRecord(evGate, 0);
    scatter_kernel<<<1, 1024>>>();

    // shared chain on s2 (needs convert [stream order] + gate's g_xh)
    cudaStreamWaitEvent(s2, evGate, 0);
    swiglu_gemm<<<dim3(T / 64, SI / 128, 1), 256, SMEM_SW, s2>>>(1);
    down_gemm<<<dim3(T / 128, DIMC / 128, 1), 256, SMEM_DN, s2>>>(1, out);
    cudaEventRecord(evShared, s2);

    // routed chain on main (needs convert)
    cudaStreamWaitEvent(0, evConv, 0);
    swiglu_gemm<<<dim3(T / 64, INTER / 128, E), 256, SMEM_SW>>>(0);
    down_gemm<<<dim3(T / 128, DIMC / 128, E), 256, SMEM_DN>>>(0, nullptr);

    // join: combine needs both chains
    cudaStreamWaitEvent(0, evShared, 0);
    combine_kernel<<<T, 256>>>(out);
}

// round 16
// speedup vs baseline: 1.9358x; 1.0176x over previous
#include <cuda_runtime.h>
#include <cuda_fp16.h>
#include <cstdint>
#include <math.h>

// ---------------------------------------------------------------------------
// MoE via fp16 mma.sync m16n8k16, cp.async(cg) 4-stage pipeline, ldmatrix,
// conflict-free (row>>1) XOR swizzle. Three-chain graph-captured overlap:
//   main: gate -> scatter -> swiglu_r(E0-7) -> down_r(E0-7) -> [join] combine
//   s2:   convert -> [gate] swiglu_sh -> down_sh(out)
//   s3:   [conv+scatter] swiglu_r(E8-15) -> down_r(E8-15)
// ---------------------------------------------------------------------------

namespace {
constexpr int T     = 2048;
constexpr int DIMC  = 1024;
constexpr int E     = 16;
constexpr int NP    = T * 2;
constexpr int INTER = 512;
constexpr int SI    = 1024;

constexpr int BK = 32;               // halves per stage (2 k16 groups)
constexpr int STAGES = 4;
constexpr int SW_ASTG = 64 * 64;
constexpr int SW_BSTG = 128 * 64;
constexpr int SMEM_SW = STAGES * (SW_ASTG + 2 * SW_BSTG);   // 81920
constexpr int DN_ASTG = 128 * 64;
constexpr int DN_BSTG = 128 * 64;
constexpr int SMEM_DN = STAGES * (DN_ASTG + DN_BSTG);       // 65536

constexpr size_t NX = (size_t)T * DIMC;
constexpr size_t NW = (size_t)E * INTER * DIMC;
constexpr size_t NS = (size_t)SI * DIMC;
constexpr size_t GW = NW / 16;
constexpr size_t GS = NS / 16;
}

__device__ int   g_count[E];
__device__ int   g_offset[E];
__device__ int   g_pair_e[NP];
__device__ float g_pair_w[NP];
__device__ int   g_slot_of_pair[NP];
__device__ int   g_tok_of_slot[NP];
__device__ __align__(16) __half g_xh[NX];
__device__ __align__(16) __half g_w1h[NW];
__device__ __align__(16) __half g_w2h[NW];
__device__ __align__(16) __half g_w3h[NW];
__device__ __align__(16) __half g_sw1h[NS];
__device__ __align__(16) __half g_sw2h[NS];
__device__ __align__(16) __half g_sw3h[NS];
__device__ __align__(16) __half g_h[(size_t)NP * INTER];
__device__ __align__(16) __half g_hs[(size_t)T * SI];
__device__ __align__(16) float  g_rout[(size_t)NP * DIMC];

// ---------------- helpers ----------------
__device__ __forceinline__ uint32_t smem_u32(const void* p) {
    uint32_t a;
    asm("{ .reg .u64 t; cvta.to.shared.u64 t, %1; cvt.u32.u64 %0, t; }" : "=r"(a) : "l"(p));
    return a;
}
__device__ __forceinline__ void mma16(float* c, const uint32_t* a, const uint32_t* b) {
    asm volatile(
        "mma.sync.aligned.m16n8k16.row.col.f32.f16.f16.f32 "
        "{%0,%1,%2,%3},{%4,%5,%6,%7},{%8,%9},{%0,%1,%2,%3};"
        : "+f"(c[0]), "+f"(c[1]), "+f"(c[2]), "+f"(c[3])
        : "r"(a[0]), "r"(a[1]), "r"(a[2]), "r"(a[3]), "r"(b[0]), "r"(b[1]));
}
#define LDSM4(r0, r1, r2, r3, addr) \
    asm volatile("ldmatrix.sync.aligned.m8n8.x4.shared.b16 {%0,%1,%2,%3}, [%4];" \
        : "=r"(r0), "=r"(r1), "=r"(r2), "=r"(r3) : "r"(addr))
#define CP_A16(dst, src) asm volatile("cp.async.cg.shared.global [%0], [%1], 16;" :: "r"(dst), "l"(src))
#define CP_COMMIT()      asm volatile("cp.async.commit_group;" ::: "memory")
#define CP_WAIT2()       asm volatile("cp.async.wait_group 2;" ::: "memory")

// conflict-free swizzle: 64B rows, 4x16B chunks, key = (row>>1)&3
__device__ __forceinline__ uint32_t soff(int row, int c) {
    return (uint32_t)(row * 64 + ((c ^ ((row >> 1) & 3)) << 4));
}

// ---------------- convert weights -> fp16 ----------------
__global__ __launch_bounds__(256) void convert_kernel(
    const float* __restrict__ w1, const float* __restrict__ w2,
    const float* __restrict__ w3, const float* __restrict__ sw1,
    const float* __restrict__ sw2, const float* __restrict__ sw3) {
    size_t g = (size_t)blockIdx.x * 256 + threadIdx.x;
    const float* src;
    __half* dst;
    size_t off;
    if      (g < GW)              { src = w1;  dst = g_w1h;  off = g; }
    else if (g < 2 * GW)          { src = w2;  dst = g_w2h;  off = g - GW; }
    else if (g < 3 * GW)          { src = w3;  dst = g_w3h;  off = g - 2 * GW; }
    else if (g < 3 * GW + GS)     { src = sw1; dst = g_sw1h; off = g - 3 * GW; }
    else if (g < 3 * GW + 2 * GS) { src = sw2; dst = g_sw2h; off = g - 3 * GW - GS; }
    else if (g < 3 * GW + 3 * GS) { src = sw3; dst = g_sw3h; off = g - 3 * GW - 2 * GS; }
    else return;
    const float4* s4 = (const float4*)(src + off * 16);
    float4 v0 = s4[0], v1 = s4[1], v2 = s4[2], v3 = s4[3];
    __align__(16) __half tmp[16];
    tmp[0]=__float2half_rn(v0.x); tmp[1]=__float2half_rn(v0.y);
    tmp[2]=__float2half_rn(v0.z); tmp[3]=__float2half_rn(v0.w);
    tmp[4]=__float2half_rn(v1.x); tmp[5]=__float2half_rn(v1.y);
    tmp[6]=__float2half_rn(v1.z); tmp[7]=__float2half_rn(v1.w);
    tmp[8]=__float2half_rn(v2.x); tmp[9]=__float2half_rn(v2.y);
    tmp[10]=__float2half_rn(v2.z); tmp[11]=__float2half_rn(v2.w);
    tmp[12]=__float2half_rn(v3.x); tmp[13]=__float2half_rn(v3.y);
    tmp[14]=__float2half_rn(v3.z); tmp[15]=__float2half_rn(v3.w);
    *(uint4*)(dst + off * 16)     = *(uint4*)tmp;
    *(uint4*)(dst + off * 16 + 8) = *(uint4*)(tmp + 8);
}

// ---------------- routing (+ fp16 x) ----------------
__global__ __launch_bounds__(128) void gate_kernel(const float* __restrict__ x,
                                                   const float* __restrict__ gw) {
    __shared__ float xs[DIMC];
    __shared__ float part[8][E];
    __shared__ float logit[E];
    int t = blockIdx.x;
    for (int i = threadIdx.x; i < DIMC; i += 128) xs[i] = x[(size_t)t * DIMC + i];
    __syncthreads();
    for (int i = threadIdx.x; i < DIMC; i += 128)
        g_xh[(size_t)t * DIMC + i] = __float2half_rn(xs[i]);

    int e = threadIdx.x & 15, chunk = threadIdx.x >> 4;
    const float* gr = gw + (size_t)e * DIMC + chunk * 128;
    const float* xr = xs + chunk * 128;
    float a0 = 0.f, a1 = 0.f, a2 = 0.f, a3 = 0.f;
    #pragma unroll 8
    for (int i = 0; i < 128; i += 4) {
        a0 += xr[i+0] * gr[i+0]; a1 += xr[i+1] * gr[i+1];
        a2 += xr[i+2] * gr[i+2]; a3 += xr[i+3] * gr[i+3];
    }
    part[chunk][e] = (a0 + a1) + (a2 + a3);
    __syncthreads();
    if (threadIdx.x < E) {
        float s = 0.f;
        #pragma unroll
        for (int c = 0; c < 8; c++) s += part[c][threadIdx.x];
        logit[threadIdx.x] = s;
    }
    __syncthreads();
    if (threadIdx.x == 0) {
        int i0 = 0; float v0 = logit[0];
        #pragma unroll
        for (int i = 1; i < E; i++) if (logit[i] > v0) { v0 = logit[i]; i0 = i; }
        int i1 = -1; float v1 = -1e30f;
        #pragma unroll
        for (int i = 0; i < E; i++) if (i != i0 && logit[i] > v1) { v1 = logit[i]; i1 = i; }
        float s0 = 1.f / (1.f + expf(-v0));
        float s1 = 1.f / (1.f + expf(-v1));
        float inv = 1.f / (s0 + s1);
        g_pair_e[t*2+0] = i0; g_pair_w[t*2+0] = s0 * inv;
        g_pair_e[t*2+1] = i1; g_pair_w[t*2+1] = s1 * inv;
    }
}

__global__ __launch_bounds__(1024) void scatter_kernel() {
    __shared__ int cnt[E], off[E], fill[E];
    if (threadIdx.x < E) { cnt[threadIdx.x] = 0; fill[threadIdx.x] = 0; }
    __syncthreads();
    for (int p = threadIdx.x; p < NP; p += 1024)
        atomicAdd(&cnt[g_pair_e[p]], 1);
    __syncthreads();
    if (threadIdx.x == 0) {
        int s = 0;
        #pragma unroll
        for (int e = 0; e < E; e++) {
            off[e] = s; g_offset[e] = s; g_count[e] = cnt[e]; s += cnt[e];
        }
    }
    __syncthreads();
    for (int p = threadIdx.x; p < NP; p += 1024) {
        int e = g_pair_e[p];
        int slot = off[e] + atomicAdd(&fill[e], 1);
        g_slot_of_pair[p] = slot;
        g_tok_of_slot[slot] = p >> 1;
    }
}

// ---------------------------------------------------------------------------
// SwiGLU GEMM fp16: BM=64, BN=128, dual-B, ldmatrix.
// shared_mode: 1 -> shared expert; else routed, expert = zoff + blockIdx.z
// ---------------------------------------------------------------------------
__global__ __launch_bounds__(256, 2) void swiglu_gemm(int shared_mode, int zoff) {
    extern __shared__ uint32_t sm[];
    __shared__ int rowsS[64];

    const bool routed = !shared_mode;
    const int  z      = routed ? (zoff + blockIdx.z) : 0;
    const int  Ntot   = routed ? INTER : SI;
    const int cnt  = routed ? g_count[z] : T;
    const int m0   = blockIdx.x * 64;
    if (m0 >= cnt) return;
    const int n0   = blockIdx.y * 128;
    const int base = routed ? g_offset[z] : 0;

    const __half* B1 = routed ? (g_w1h + (size_t)z * INTER * DIMC) : g_sw1h;
    const __half* B3 = routed ? (g_w3h + (size_t)z * INTER * DIMC) : g_sw3h;
    __half* C = routed ? g_h : g_hs;

    const int tid    = threadIdx.x;
    const int wid    = tid >> 5;
    const int lane   = tid & 31;
    const int lane4  = lane >> 2;
    const int lanek  = lane & 3;
    const int warp_m = wid & 1;
    const int warp_n = wid >> 1;

    if (tid < 64) {
        int m = m0 + tid;
        rowsS[tid] = routed ? g_tok_of_slot[base + min(m, cnt - 1)]
                            : min(m, cnt - 1);
    }
    __syncthreads();

    const uint32_t smA = smem_u32(sm);
    const uint32_t smB = smA + STAGES * SW_ASTG;
    const uint32_t smC = smB + STAGES * SW_BSTG;

    const int ar = tid >> 2, ac = tid & 3;
    const __half* asrc = g_xh + (size_t)rowsS[ar] * DIMC + ac * 8;
    const __half* b1s0 = B1 + (size_t)(n0 + ar) * DIMC + ac * 8;
    const __half* b1s1 = B1 + (size_t)(n0 + 64 + ar) * DIMC + ac * 8;
    const __half* b3s0 = B3 + (size_t)(n0 + ar) * DIMC + ac * 8;
    const __half* b3s1 = B3 + (size_t)(n0 + 64 + ar) * DIMC + ac * 8;
    const uint32_t adst  = smA + soff(ar, ac);
    const uint32_t bdst0 = smB + soff(ar, ac);
    const uint32_t bdst1 = smB + soff(64 + ar, ac);
    const uint32_t cdst0 = smC + soff(ar, ac);
    const uint32_t cdst1 = smC + soff(64 + ar, ac);

    auto issue = [&](int k0, int st) {
        if (k0 < DIMC) {
            CP_A16(adst  + st * SW_ASTG, asrc + k0);
            CP_A16(bdst0 + st * SW_BSTG, b1s0 + k0);
            CP_A16(bdst1 + st * SW_BSTG, b1s1 + k0);
            CP_A16(cdst0 + st * SW_BSTG, b3s0 + k0);
            CP_A16(cdst1 + st * SW_BSTG, b3s1 + k0);
        }
        CP_COMMIT();
    };

    issue(0, 0); issue(BK, 1); issue(2 * BK, 2);

    const int mat  = lane >> 3, mrow = lane & 7;
    const int cbA  = mat >> 1;
    const int cbB  = mat & 1;
    int arow[2], akey[2], brow[2], bkey[2];
    #pragma unroll
    for (int fm = 0; fm < 2; fm++) {
        int r = warp_m * 32 + fm * 16 + ((mat & 1) << 3) + mrow;
        arow[fm] = r * 64; akey[fm] = (r >> 1) & 3;
    }
    #pragma unroll
    for (int fn2 = 0; fn2 < 2; fn2++) {
        int r = warp_n * 32 + fn2 * 16 + ((mat >> 1) << 3) + mrow;
        brow[fn2] = r * 64; bkey[fn2] = (r >> 1) & 3;
    }

    float acc1[2][4][4] = {};
    float acc3[2][4][4] = {};

    int st = 0;
    for (int k0 = 0; k0 < DIMC; k0 += BK) {
        CP_WAIT2();
        __syncthreads();
        const uint32_t aSt = smA + st * SW_ASTG;
        const uint32_t bSt = smB + st * SW_BSTG;
        const uint32_t cSt = smC + st * SW_BSTG;

        #pragma unroll
        for (int g = 0; g < 2; g++) {
            uint32_t af[2][4];
            #pragma unroll
            for (int fm = 0; fm < 2; fm++) {
                uint32_t ad = aSt + arow[fm] + ((((g << 1) + cbA) ^ akey[fm]) << 4);
                LDSM4(af[fm][0], af[fm][1], af[fm][2], af[fm][3], ad);
            }
            #pragma unroll
            for (int fn2 = 0; fn2 < 2; fn2++) {
                uint32_t boff = brow[fn2] + ((((g << 1) + cbB) ^ bkey[fn2]) << 4);
                uint32_t bf[4], cf[4];
                LDSM4(bf[0], bf[1], bf[2], bf[3], bSt + boff);
                LDSM4(cf[0], cf[1], cf[2], cf[3], cSt + boff);
                mma16(acc1[0][fn2 * 2 + 0], af[0], bf + 0);
                mma16(acc1[0][fn2 * 2 + 1], af[0], bf + 2);
                mma16(acc1[1][fn2 * 2 + 0], af[1], bf + 0);
                mma16(acc1[1][fn2 * 2 + 1], af[1], bf + 2);
                mma16(acc3[0][fn2 * 2 + 0], af[0], cf + 0);
                mma16(acc3[0][fn2 * 2 + 1], af[0], cf + 2);
                mma16(acc3[1][fn2 * 2 + 0], af[1], cf + 0);
                mma16(acc3[1][fn2 * 2 + 1], af[1], cf + 2);
            }
        }
        issue(k0 + 3 * BK, (k0 / BK + 3) & (STAGES - 1));
        st = (st + 1) & (STAGES - 1);
    }

    #pragma unroll
    for (int fm = 0; fm < 2; fm++) {
        #pragma unroll
        for (int half = 0; half < 2; half++) {
            int mi = warp_m * 32 + fm * 16 + half * 8 + lane4;
            int m  = m0 + mi;
            if (m >= cnt) continue;
            size_t crow = routed ? (size_t)(base + m) : (size_t)m;
            #pragma unroll
            for (int fn = 0; fn < 4; fn++) {
                int c = n0 + warp_n * 32 + fn * 8 + lanek * 2;
                float v0 = acc1[fm][fn][half * 2 + 0];
                float v1 = acc1[fm][fn][half * 2 + 1];
                float sx = (v0 / (1.f + __expf(-v0))) * acc3[fm][fn][half * 2 + 0];
                float sy = (v1 / (1.f + __expf(-v1))) * acc3[fm][fn][half * 2 + 1];
                *(__half2*)(C + crow * Ntot + c) = __floats2half2_rn(sx, sy);
            }
        }
    }
}

// ---------------------------------------------------------------------------
// Down GEMM fp16: BM=128, BN=128, warp 64x32, ldmatrix.
// ---------------------------------------------------------------------------
__global__ __launch_bounds__(256, 2) void down_gemm(int shared_mode, int zoff,
                                                    float* __restrict__ out) {
    extern __shared__ uint32_t sm[];
    __shared__ int rowsS[128];

    const bool routed = !shared_mode;
    const int  z      = routed ? (zoff + blockIdx.z) : 0;
    const int  KD     = routed ? INTER : SI;
    const int cnt  = routed ? g_count[z] : T;
    const int m0   = blockIdx.x * 128;
    if (m0 >= cnt) return;
    const int n0   = blockIdx.y * 128;
    const int base = routed ? g_offset[z] : 0;

    const __half* A  = routed ? g_h : g_hs;
    const __half* B1 = routed ? (g_w2h + (size_t)z * DIMC * INTER) : g_sw2h;
    float* C = routed ? g_rout : out;

    const int tid    = threadIdx.x;
    const int wid    = tid >> 5;
    const int lane   = tid & 31;
    const int lane4  = lane >> 2;
    const int lanek  = lane & 3;
    const int warp_m = wid & 1;
    const int warp_n = wid >> 1;

    if (tid < 128) {
        int mm = m0 + tid;
        if (mm >= cnt) mm = cnt - 1;
        rowsS[tid] = routed ? (base + mm) : mm;
    }
    __syncthreads();

    const uint32_t smA = smem_u32(sm);
    const uint32_t smB = smA + STAGES * DN_ASTG;

    const int ar0 = tid >> 2, ar1 = 64 + (tid >> 2), ac = tid & 3;
    const __half* asrc0 = A  + (size_t)rowsS[ar0] * KD + ac * 8;
    const __half* asrc1 = A  + (size_t)rowsS[ar1] * KD + ac * 8;
    const __half* bsrc0 = B1 + (size_t)(n0 + ar0) * KD + ac * 8;
    const __half* bsrc1 = B1 + (size_t)(n0 + ar1) * KD + ac * 8;
    const uint32_t adst0 = smA + soff(ar0, ac);
    const uint32_t adst1 = smA + soff(ar1, ac);
    const uint32_t bdst0 = smB + soff(ar0, ac);
    const uint32_t bdst1 = smB + soff(ar1, ac);

    auto issue = [&](int k0, int st) {
        if (k0 < KD) {
            CP_A16(adst0 + st * DN_ASTG, asrc0 + k0);
            CP_A16(adst1 + st * DN_ASTG, asrc1 + k0);
            CP_A16(bdst0 + st * DN_BSTG, bsrc0 + k0);
            CP_A16(bdst1 + st * DN_BSTG, bsrc1 + k0);
        }
        CP_COMMIT();
    };

    issue(0, 0); issue(BK, 1); issue(2 * BK, 2);

    const int mat  = lane >> 3, mrow = lane & 7;
    const int cbA  = mat >> 1;
    const int cbB  = mat & 1;
    int arow[4], akey[4], brow[2], bkey[2];
    #pragma unroll
    for (int fm = 0; fm < 4; fm++) {
        int r = warp_m * 64 + fm * 16 + ((mat & 1) << 3) + mrow;
        arow[fm] = r * 64; akey[fm] = (r >> 1) & 3;
    }
    #pragma unroll
    for (int fn2 = 0; fn2 < 2; fn2++) {
        int r = warp_n * 32 + fn2 * 16 + ((mat >> 1) << 3) + mrow;
        brow[fn2] = r * 64; bkey[fn2] = (r >> 1) & 3;
    }

    float acc[4][4][4] = {};

    int st = 0;
    for (int k0 = 0; k0 < KD; k0 += BK) {
        CP_WAIT2();
        __syncthreads();
        const uint32_t aSt = smA + st * DN_ASTG;
        const uint32_t bSt = smB + st * DN_BSTG;

        #pragma unroll
        for (int g = 0; g < 2; g++) {
            uint32_t af[4][4];
            #pragma unroll
            for (int fm = 0; fm < 4; fm++) {
                uint32_t ad = aSt + arow[fm] + ((((g << 1) + cbA) ^ akey[fm]) << 4);
                LDSM4(af[fm][0], af[fm][1], af[fm][2], af[fm][3], ad);
            }
            #pragma unroll
            for (int fn2 = 0; fn2 < 2; fn2++) {
                uint32_t bf[4];
                uint32_t boff = brow[fn2] + ((((g << 1) + cbB) ^ bkey[fn2]) << 4);
                LDSM4(bf[0], bf[1], bf[2], bf[3], bSt + boff);
                #pragma unroll
                for (int fm = 0; fm < 4; fm++) {
                    mma16(acc[fm][fn2 * 2 + 0], af[fm], bf + 0);
                    mma16(acc[fm][fn2 * 2 + 1], af[fm], bf + 2);
                }
            }
        }
        issue(k0 + 3 * BK, (k0 / BK + 3) & (STAGES - 1));
        st = (st + 1) & (STAGES - 1);
    }

    #pragma unroll
    for (int fm = 0; fm < 4; fm++) {
        #pragma unroll
        for (int half = 0; half < 2; half++) {
            int mi = warp_m * 64 + fm * 16 + half * 8 + lane4;
            int m  = m0 + mi;
            if (m >= cnt) continue;
            size_t crow = routed ? (size_t)(base + m) : (size_t)m;
            float* cp = C + crow * DIMC + n0 + warp_n * 32 + lanek * 2;
            #pragma unroll
            for (int fn = 0; fn < 4; fn++) {
                float2 o;
                o.x = acc[fm][fn][half * 2 + 0];
                o.y = acc[fm][fn][half * 2 + 1];
                *(float2*)(cp + fn * 8) = o;
            }
        }
    }
}

__global__ __launch_bounds__(256) void combine_kernel(float* __restrict__ out) {
    int t = blockIdx.x;
    float w0 = g_pair_w[t*2+0], w1 = g_pair_w[t*2+1];
    size_t s0 = (size_t)g_slot_of_pair[t*2+0] * DIMC;
    size_t s1 = (size_t)g_slot_of_pair[t*2+1] * DIMC;
    int d = threadIdx.x * 4;
    float4 o  = *(float4*)(out + (size_t)t * DIMC + d);
    float4 r0 = *(const float4*)(g_rout + s0 + d);
    float4 r1 = *(const float4*)(g_rout + s1 + d);
    o.x += w0 * r0.x + w1 * r1.x;
    o.y += w0 * r0.y + w1 * r1.y;
    o.z += w0 * r0.z + w1 * r1.z;
    o.w += w0 * r0.w + w1 * r1.w;
    *(float4*)(out + (size_t)t * DIMC + d) = o;
}

// ---------------------------------------------------------------------------
extern "C" void kernel_launch(void* const* d_in, const int* in_sizes, int n_in,
                              void* d_out, int out_size) {
    const float* x      = (const float*)d_in[0];
    const float* gate_w = (const float*)d_in[1];
    const float* w1     = (const float*)d_in[2];
    const float* w2     = (const float*)d_in[3];
    const float* w3     = (const float*)d_in[4];
    const float* sw1    = (const float*)d_in[5];
    const float* sw2    = (const float*)d_in[6];
    const float* sw3    = (const float*)d_in[7];
    float* out = (float*)d_out;

    static cudaStream_t s2 = nullptr, s3 = nullptr;
    static cudaEvent_t evFork, evConv, evGate, evScat, evShared, evR2;
    if (s2 == nullptr) {
        cudaStreamCreateWithFlags(&s2, cudaStreamNonBlocking);
        cudaStreamCreateWithFlags(&s3, cudaStreamNonBlocking);
        cudaEventCreateWithFlags(&evFork,   cudaEventDisableTiming);
        cudaEventCreateWithFlags(&evConv,   cudaEventDisableTiming);
        cudaEventCreateWithFlags(&evGate,   cudaEventDisableTiming);
        cudaEventCreateWithFlags(&evScat,   cudaEventDisableTiming);
        cudaEventCreateWithFlags(&evShared, cudaEventDisableTiming);
        cudaEventCreateWithFlags(&evR2,     cudaEventDisableTiming);
        cudaFuncSetAttribute(swiglu_gemm, cudaFuncAttributeMaxDynamicSharedMemorySize, SMEM_SW);
        cudaFuncSetAttribute(down_gemm,   cudaFuncAttributeMaxDynamicSharedMemorySize, SMEM_DN);
    }

    // fork
    cudaEventRecord(evFork, 0);
    cudaStreamWaitEvent(s2, evFork, 0);
    cudaStreamWaitEvent(s3, evFork, 0);

    // s2: convert weights
    size_t ngroups = 3 * GW + 3 * GS;
    convert_kernel<<<(int)((ngroups + 255) / 256), 256, 0, s2>>>(w1, w2, w3, sw1, sw2, sw3);
    cudaEventRecord(evConv, s2);

    // main: routing
    gate_kernel<<<T, 128>>>(x, gate_w);
    cudaEventRecord(evGate, 0);
    scatter_kernel<<<1, 1024>>>();
    cudaEventRecord(evScat, 0);

    // s2: shared chain (convert done by stream order; needs g_xh from gate)
    cudaStreamWaitEvent(s2, evGate, 0);
    swiglu_gemm<<<dim3(T / 64, SI / 128, 1), 256, SMEM_SW, s2>>>(1, 0);
    down_gemm<<<dim3(T / 128, DIMC / 128, 1), 256, SMEM_DN, s2>>>(1, 0, out);
    cudaEventRecord(evShared, s2);

    // s3: routed chain, experts 8..15 (needs convert + scatter)
    cudaStreamWaitEvent(s3, evConv, 0);
    cudaStreamWaitEvent(s3, evScat, 0);
    swiglu_gemm<<<dim3(T / 64, INTER / 128, E / 2), 256, SMEM_SW, s3>>>(0, E / 2);
    down_gemm<<<dim3(T / 128, DIMC / 128, E / 2), 256, SMEM_DN, s3>>>(0, E / 2, nullptr);
    cudaEventRecord(evR2, s3);

    // main: routed chain, experts 0..7 (needs convert; scatter by stream order)
    cudaStreamWaitEvent(0, evConv, 0);
    swiglu_gemm<<<dim3(T / 64, INTER / 128, E / 2), 256, SMEM_SW>>>(0, 0);
    down_gemm<<<dim3(T / 128, DIMC / 128, E / 2), 256, SMEM_DN>>>(0, 0, nullptr);

    // join
    cudaStreamWaitEvent(0, evShared, 0);
    cudaStreamWaitEvent(0, evR2, 0);
    combine_kernel<<<T, 256>>>(out);
}